// round 1
// baseline (speedup 1.0000x reference)
#include <cuda_runtime.h>
#include <cuda_bf16.h>
#include <cstdint>

// Problem constants
#define BATCH 4
#define SEQ   2048
#define FDIM  512
#define EDIM  512
#define HEADS 8
#define DH    64
#define MROWS (BATCH*SEQ)      // 8192

// Scratch: Q/K/V in [B,H,S,DH] (head-major) layout
__device__ float g_q[(size_t)BATCH*HEADS*SEQ*DH];
__device__ float g_k[(size_t)BATCH*HEADS*SEQ*DH];
__device__ float g_v[(size_t)BATCH*HEADS*SEQ*DH];

// ---------------------------------------------------------------------------
// Fused QKV projection GEMM: C[8192 x 1536] = x[8192x512] @ [Wq|Wk|Wv] + bias
// (+ etype_emb for the Q third). Output scattered to head-major scratch.
// 128x128 block tile, BK=16, 256 threads, 8x8 microtile.
// ---------------------------------------------------------------------------
#define BM 128
#define BN 128
#define BK 16
#define TM 8
#define TN 8

__global__ __launch_bounds__(256)
void qkv_gemm(const float* __restrict__ x,
              const float* __restrict__ etype,
              const float* __restrict__ Wq, const float* __restrict__ bq,
              const float* __restrict__ Wk, const float* __restrict__ bk,
              const float* __restrict__ Wv, const float* __restrict__ bv)
{
    __shared__ float As[BK][BM];   // A transposed: As[k][m]
    __shared__ float Bs[BK][BN];

    const int bx = blockIdx.x;          // 64 M-tiles
    const int by = blockIdx.y;          // 12 N-tiles over 1536
    const int n0 = by * BN;
    const int which = n0 >> 9;          // 0=q,1=k,2=v (BN=128 divides 512)
    const int e0 = n0 & 511;

    const float* W; const float* bias; float* outbuf;
    if (which == 0)      { W = Wq; bias = bq; outbuf = g_q; }
    else if (which == 1) { W = Wk; bias = bk; outbuf = g_k; }
    else                 { W = Wv; bias = bv; outbuf = g_v; }

    const int tid = threadIdx.x;
    const int tx = tid & 15;
    const int ty = tid >> 4;
    const int m0 = bx * BM;

    // A-load mapping: 128 rows x 16 cols -> 512 float4 / 256 thr = 2 each
    const int a_row  = tid >> 2;         // 0..63 (+64)
    const int a_col4 = (tid & 3) * 4;    // 0,4,8,12
    // B-load mapping: 16 rows x 128 cols -> 512 float4 / 256 thr = 2 each
    const int b_row  = tid >> 5;         // 0..7 (+8)
    const int b_col4 = (tid & 31) * 4;

    float acc[TM][TN];
    #pragma unroll
    for (int i = 0; i < TM; i++)
        #pragma unroll
        for (int j = 0; j < TN; j++) acc[i][j] = 0.f;

    for (int k0 = 0; k0 < FDIM; k0 += BK) {
        #pragma unroll
        for (int r = 0; r < 2; r++) {
            int row = a_row + r * 64;
            float4 v = *(const float4*)&x[(size_t)(m0 + row) * FDIM + k0 + a_col4];
            As[a_col4 + 0][row] = v.x;
            As[a_col4 + 1][row] = v.y;
            As[a_col4 + 2][row] = v.z;
            As[a_col4 + 3][row] = v.w;
        }
        #pragma unroll
        for (int r = 0; r < 2; r++) {
            int row = b_row + r * 8;
            *(float4*)&Bs[row][b_col4] =
                *(const float4*)&W[(size_t)(k0 + row) * EDIM + e0 + b_col4];
        }
        __syncthreads();

        #pragma unroll
        for (int kk = 0; kk < BK; kk++) {
            float a[TM], b[TN];
            float4 a0 = *(const float4*)&As[kk][ty * TM];
            float4 a1 = *(const float4*)&As[kk][ty * TM + 4];
            a[0]=a0.x; a[1]=a0.y; a[2]=a0.z; a[3]=a0.w;
            a[4]=a1.x; a[5]=a1.y; a[6]=a1.z; a[7]=a1.w;
            float4 b0 = *(const float4*)&Bs[kk][tx * TN];
            float4 b1 = *(const float4*)&Bs[kk][tx * TN + 4];
            b[0]=b0.x; b[1]=b0.y; b[2]=b0.z; b[3]=b0.w;
            b[4]=b1.x; b[5]=b1.y; b[6]=b1.z; b[7]=b1.w;
            #pragma unroll
            for (int i = 0; i < TM; i++)
                #pragma unroll
                for (int j = 0; j < TN; j++)
                    acc[i][j] += a[i] * b[j];
        }
        __syncthreads();
    }

    // Epilogue: bias (+etype for Q), scatter to [B,H,S,DH]
    #pragma unroll
    for (int i = 0; i < TM; i++) {
        int m = m0 + ty * TM + i;
        int b_idx = m >> 11;            // / SEQ
        int s_idx = m & 2047;
        #pragma unroll
        for (int j = 0; j < TN; j++) {
            int e = e0 + tx * TN + j;
            float c = acc[i][j] + bias[e];
            if (which == 0) c += etype[(size_t)m * EDIM + e];
            int h = e >> 6, d = e & 63;
            outbuf[(((size_t)(b_idx * HEADS + h)) * SEQ + s_idx) * DH + d] = c;
        }
    }
}

// ---------------------------------------------------------------------------
// Flash-style attention: one thread = one query row (q + acc in registers),
// K/V staged in SMEM (broadcast reads), online softmax with lazy rescale.
// Grid: (SEQ/128, B*H), 128 threads.
// ---------------------------------------------------------------------------
#define AQ 128
#define AK 64

__global__ __launch_bounds__(128)
void attn_kernel(const int* __restrict__ mask, float* __restrict__ out)
{
    __shared__ float ks[AK][DH];
    __shared__ float vs[AK][DH];
    __shared__ float keep[AK];      // 1 = keep, 0 = masked

    const int bh = blockIdx.y;                   // 0..31
    const int b  = bh >> 3;
    const int h  = bh & 7;
    const int sq = blockIdx.x * AQ + threadIdx.x;

    // Load q row, pre-scaled by 1/sqrt(DH)
    const float* qptr = g_q + ((size_t)bh * SEQ + sq) * DH;
    float q[DH];
    #pragma unroll
    for (int d = 0; d < DH; d += 4) {
        float4 t = *(const float4*)&qptr[d];
        q[d+0] = t.x * 0.125f; q[d+1] = t.y * 0.125f;
        q[d+2] = t.z * 0.125f; q[d+3] = t.w * 0.125f;
    }

    float m_i = -3.0e38f;
    float l_i = 0.f;
    float acc[DH];
    #pragma unroll
    for (int d = 0; d < DH; d++) acc[d] = 0.f;

    const float4* kbase4 = (const float4*)(g_k + (size_t)bh * SEQ * DH);
    const float4* vbase4 = (const float4*)(g_v + (size_t)bh * SEQ * DH);

    for (int k0 = 0; k0 < SEQ; k0 += AK) {
        __syncthreads();
        // Stage K/V tile: 64x64 floats = 1024 float4 each, 8 per thread
        size_t base4 = (size_t)k0 * (DH / 4);
        #pragma unroll
        for (int i = 0; i < 8; i++) {
            int idx = threadIdx.x + i * 128;
            ((float4*)ks)[idx] = kbase4[base4 + idx];
            ((float4*)vs)[idx] = vbase4[base4 + idx];
        }
        if (threadIdx.x < AK)
            keep[threadIdx.x] = (mask[b * SEQ + k0 + threadIdx.x] == 1) ? 1.f : 0.f;
        __syncthreads();

        for (int j = 0; j < AK; j++) {
            // score = q . k[j]  (tree of 4 partials)
            const float4* kr = (const float4*)ks[j];
            float s0 = 0.f, s1 = 0.f, s2 = 0.f, s3 = 0.f;
            #pragma unroll
            for (int d4 = 0; d4 < 16; d4 += 4) {
                float4 k0v = kr[d4+0], k1v = kr[d4+1], k2v = kr[d4+2], k3v = kr[d4+3];
                s0 += q[(d4+0)*4+0]*k0v.x + q[(d4+0)*4+1]*k0v.y + q[(d4+0)*4+2]*k0v.z + q[(d4+0)*4+3]*k0v.w;
                s1 += q[(d4+1)*4+0]*k1v.x + q[(d4+1)*4+1]*k1v.y + q[(d4+1)*4+2]*k1v.z + q[(d4+1)*4+3]*k1v.w;
                s2 += q[(d4+2)*4+0]*k2v.x + q[(d4+2)*4+1]*k2v.y + q[(d4+2)*4+2]*k2v.z + q[(d4+2)*4+3]*k2v.w;
                s3 += q[(d4+3)*4+0]*k3v.x + q[(d4+3)*4+1]*k3v.y + q[(d4+3)*4+2]*k3v.z + q[(d4+3)*4+3]*k3v.w;
            }
            float s = (s0 + s1) + (s2 + s3);
            s = (keep[j] != 0.f) ? s : -1e10f;

            if (s > m_i) {                       // rare after warm-up
                float corr = __expf(m_i - s);
                m_i = s;
                l_i *= corr;
                #pragma unroll
                for (int d = 0; d < DH; d++) acc[d] *= corr;
            }
            float p = __expf(s - m_i);
            l_i += p;

            const float4* vr = (const float4*)vs[j];
            #pragma unroll
            for (int d4 = 0; d4 < 16; d4++) {
                float4 vv = vr[d4];
                acc[d4*4+0] += p * vv.x;
                acc[d4*4+1] += p * vv.y;
                acc[d4*4+2] += p * vv.z;
                acc[d4*4+3] += p * vv.w;
            }
        }
    }

    // Query mask: zero masked query rows; normalize by l
    float qm  = (mask[b * SEQ + sq] == 1) ? 1.f : 0.f;
    float inv = qm / l_i;
    float* op = out + ((size_t)b * SEQ + sq) * EDIM + h * DH;
    #pragma unroll
    for (int d = 0; d < DH; d += 4) {
        float4 t;
        t.x = acc[d+0] * inv; t.y = acc[d+1] * inv;
        t.z = acc[d+2] * inv; t.w = acc[d+3] * inv;
        *(float4*)&op[d] = t;
    }
}

// ---------------------------------------------------------------------------
extern "C" void kernel_launch(void* const* d_in, const int* in_sizes, int n_in,
                              void* d_out, int out_size)
{
    const float* x     = (const float*)d_in[0];
    const float* etype = (const float*)d_in[1];
    const int*   mask  = (const int*)  d_in[2];
    const float* Wq    = (const float*)d_in[3];
    const float* bq    = (const float*)d_in[4];
    const float* Wk    = (const float*)d_in[5];
    const float* bk    = (const float*)d_in[6];
    const float* Wv    = (const float*)d_in[7];
    const float* bv    = (const float*)d_in[8];
    float* out = (float*)d_out;

    dim3 ggrid(MROWS / BM, (3 * EDIM) / BN);    // 64 x 12
    qkv_gemm<<<ggrid, 256>>>(x, etype, Wq, bq, Wk, bk, Wv, bv);

    dim3 agrid(SEQ / AQ, BATCH * HEADS);        // 16 x 32
    attn_kernel<<<agrid, 128>>>(mask, out);
}

// round 3
// speedup vs baseline: 2.7078x; 2.7078x over previous
#include <cuda_runtime.h>
#include <cuda_bf16.h>
#include <cstdint>

// Problem constants
#define BATCH 4
#define SEQ   2048
#define FDIM  512
#define EDIM  512
#define HEADS 8
#define DH    64
#define MROWS (BATCH*SEQ)      // 8192

// tcgen05 only exists in arch-accelerated ('a') compilation passes. The GPU
// host build includes a plain compute_103 PTX pass which rejects tcgen05 —
// gate it and provide an fp32 fallback body for non-'a' passes.
#if defined(__CUDA_ARCH_FEAT_SM103_ALL) || defined(__CUDA_ARCH_FEAT_SM100_ALL) || \
    defined(__CUDA_ARCH_SPECIFIC__) || defined(__CUDA_ARCH_FAMILY_SPECIFIC__)
#define TC_ENABLED 1
#else
#define TC_ENABLED 0
#endif

// Scratch: Q/K in [B,H,S,DH]; V stored TRANSPOSED [B,H,DH,S] for the PV MMA.
__device__ float g_q[(size_t)BATCH*HEADS*SEQ*DH];
__device__ float g_k[(size_t)BATCH*HEADS*SEQ*DH];
__device__ float g_v[(size_t)BATCH*HEADS*DH*SEQ];

// ===========================================================================
// PTX helpers
// ===========================================================================
__device__ __forceinline__ uint32_t smem_u32(const void* p) {
    uint32_t a;
    asm("{ .reg .u64 t; cvta.to.shared.u64 t, %1; cvt.u32.u64 %0, t; }" : "=r"(a) : "l"(p));
    return a;
}
__device__ __forceinline__ bool elect_one() {
    uint32_t pred;
    asm volatile("{\n\t.reg .pred p;\n\telect.sync _|p, 0xFFFFFFFF;\n\t"
                 "selp.b32 %0, 1, 0, p;\n\t}" : "=r"(pred));
    return pred != 0;
}
// Round-to-nearest tf32 (sm_80+, legal in all passes)
__device__ __forceinline__ float rna_tf32(float x) {
    uint32_t u;
    asm("cvt.rna.tf32.f32 %0, %1;" : "=r"(u) : "f"(x));
    return __uint_as_float(u);
}
__device__ __forceinline__ uint32_t rna_tf32_bits(float x) {
    uint32_t u;
    asm("cvt.rna.tf32.f32 %0, %1;" : "=r"(u) : "f"(x));
    return u;
}

#define TC_ALLOC(smem_addr, n) \
    asm volatile("tcgen05.alloc.cta_group::1.sync.aligned.shared::cta.b32 [%0], %1;" \
                 :: "r"(smem_addr), "r"((uint32_t)(n)) : "memory")
#define TC_RELINQ() \
    asm volatile("tcgen05.relinquish_alloc_permit.cta_group::1.sync.aligned;")
#define TC_DEALLOC(tmem_addr, n) \
    asm volatile("tcgen05.dealloc.cta_group::1.sync.aligned.b32 %0, %1;" \
                 :: "r"(tmem_addr), "r"((uint32_t)(n)))
#define TC_WAIT_ST() asm volatile("tcgen05.wait::st.sync.aligned;" ::: "memory")
#define TC_WAIT_LD() asm volatile("tcgen05.wait::ld.sync.aligned;" ::: "memory")
#define TC_FENCE_BEFORE() asm volatile("tcgen05.fence::before_thread_sync;" ::: "memory")
#define TC_FENCE_AFTER()  asm volatile("tcgen05.fence::after_thread_sync;" ::: "memory")
#define TC_COMMIT(mbar) \
    asm volatile("tcgen05.commit.cta_group::1.mbarrier::arrive::one.shared::cluster.b64 [%0];" \
                 :: "r"((uint32_t)(mbar)) : "memory")

#define TC_ST_X32(tmem_addr, r) \
    asm volatile("tcgen05.st.sync.aligned.32x32b.x32.b32 [%0], " \
        "{%1, %2, %3, %4, %5, %6, %7, %8, %9, %10, %11, %12, %13, %14, %15, %16, " \
        " %17, %18, %19, %20, %21, %22, %23, %24, %25, %26, %27, %28, %29, %30, %31, %32};" \
        :: "r"(tmem_addr), \
           "r"((r)[0]),"r"((r)[1]),"r"((r)[2]),"r"((r)[3]),"r"((r)[4]),"r"((r)[5]),"r"((r)[6]),"r"((r)[7]), \
           "r"((r)[8]),"r"((r)[9]),"r"((r)[10]),"r"((r)[11]),"r"((r)[12]),"r"((r)[13]),"r"((r)[14]),"r"((r)[15]), \
           "r"((r)[16]),"r"((r)[17]),"r"((r)[18]),"r"((r)[19]),"r"((r)[20]),"r"((r)[21]),"r"((r)[22]),"r"((r)[23]), \
           "r"((r)[24]),"r"((r)[25]),"r"((r)[26]),"r"((r)[27]),"r"((r)[28]),"r"((r)[29]),"r"((r)[30]),"r"((r)[31]) \
        : "memory")

#define TC_LD_X32(r, tmem_addr) \
    asm volatile("tcgen05.ld.sync.aligned.32x32b.x32.b32 " \
        "{%0, %1, %2, %3, %4, %5, %6, %7, %8, %9, %10, %11, %12, %13, %14, %15, " \
        " %16, %17, %18, %19, %20, %21, %22, %23, %24, %25, %26, %27, %28, %29, %30, %31}, [%32];" \
        : "=r"((r)[0]),"=r"((r)[1]),"=r"((r)[2]),"=r"((r)[3]),"=r"((r)[4]),"=r"((r)[5]),"=r"((r)[6]),"=r"((r)[7]), \
          "=r"((r)[8]),"=r"((r)[9]),"=r"((r)[10]),"=r"((r)[11]),"=r"((r)[12]),"=r"((r)[13]),"=r"((r)[14]),"=r"((r)[15]), \
          "=r"((r)[16]),"=r"((r)[17]),"=r"((r)[18]),"=r"((r)[19]),"=r"((r)[20]),"=r"((r)[21]),"=r"((r)[22]),"=r"((r)[23]), \
          "=r"((r)[24]),"=r"((r)[25]),"=r"((r)[26]),"=r"((r)[27]),"=r"((r)[28]),"=r"((r)[29]),"=r"((r)[30]),"=r"((r)[31]) \
        : "r"(tmem_addr))

#define MBAR_INIT(mbar, cnt) \
    asm volatile("mbarrier.init.shared.b64 [%0], %1;" :: "r"((uint32_t)(mbar)), "r"((uint32_t)(cnt)) : "memory")

#define MBAR_WAIT(mbar, parity) do { \
    uint32_t _m = (uint32_t)(mbar); uint32_t _p = (uint32_t)(parity); uint32_t _done; \
    asm volatile("{\n\t.reg .pred p;\n\t" \
        "mbarrier.try_wait.parity.acquire.cta.shared::cta.b64 p, [%1], %2;\n\t" \
        "selp.b32 %0, 1, 0, p;\n\t}" : "=r"(_done) : "r"(_m), "r"(_p) : "memory"); \
    if (!_done) { \
        asm volatile("{\n\t.reg .pred P1;\n\t" \
            "WAIT_LOOP_%=:\n\t" \
            "mbarrier.try_wait.parity.acquire.cta.shared::cta.b64 P1, [%0], %1, 0x989680;\n\t" \
            "@P1 bra.uni WAIT_DONE_%=;\n\t" \
            "bra.uni WAIT_LOOP_%=;\n\t" \
            "WAIT_DONE_%=:\n\t}" :: "r"(_m), "r"(_p) : "memory"); \
    } \
} while (0)

// SW128 SMEM descriptor (layout=2, version=1, SBO=64, LBO=1)
#define SMEM_DESC_BASE_SW128 \
    ((uint64_t(2) << 61) | (uint64_t(1) << 46) | (uint64_t(64) << 32) | (uint64_t(1) << 16))
#define MKDESC(addr) (SMEM_DESC_BASE_SW128 | ((uint64_t)((addr) >> 4) & 0x3FFF))
#define SWZ128(o) ((o) ^ (((o) >> 3) & 0x70))

#if TC_ENABLED
// tcgen05 tf32 MMA, TS form (A in TMEM, B in SMEM)
__device__ __forceinline__ void mma_tf32_ts(uint32_t d, uint32_t a, uint64_t bdesc,
                                            uint32_t idesc, bool acc) {
    uint32_t e = acc ? 1u : 0u;
    asm volatile("{\n\t.reg .pred p;\n\tsetp.ne.u32 p, %4, 0;\n\t"
        "tcgen05.mma.cta_group::1.kind::tf32 [%0], [%1], %2, %3, p;\n\t}"
        :: "r"(d), "r"(a), "l"(bdesc), "r"(idesc), "r"(e) : "memory");
}
#endif

// idesc: dtype=F32(1@4), atype=TF32(2@7), btype=TF32(2@10), N>>3@17, M>>4@24
#define IDESC_S  ((1u<<4)|(2u<<7)|(2u<<10)|((128u/8)<<17)|((128u/16)<<24))
#define IDESC_PV ((1u<<4)|(2u<<7)|(2u<<10)|((64u/8)<<17)|((128u/16)<<24))

// ===========================================================================
// Fused QKV projection GEMM (fp32, exact). V epilogue stores transposed.
// ===========================================================================
#define BM 128
#define BN 128
#define BK 16
#define TM 8
#define TN 8

__global__ __launch_bounds__(256)
void qkv_gemm(const float* __restrict__ x,
              const float* __restrict__ etype,
              const float* __restrict__ Wq, const float* __restrict__ bq,
              const float* __restrict__ Wk, const float* __restrict__ bk,
              const float* __restrict__ Wv, const float* __restrict__ bv)
{
    __shared__ float As[BK][BM];
    __shared__ float Bs[BK][BN];

    const int bx = blockIdx.x;
    const int by = blockIdx.y;
    const int n0 = by * BN;
    const int which = n0 >> 9;          // 0=q,1=k,2=v
    const int e0 = n0 & 511;

    const float* W; const float* bias; float* outbuf;
    if (which == 0)      { W = Wq; bias = bq; outbuf = g_q; }
    else if (which == 1) { W = Wk; bias = bk; outbuf = g_k; }
    else                 { W = Wv; bias = bv; outbuf = g_v; }

    const int tid = threadIdx.x;
    const int tx = tid & 15;
    const int ty = tid >> 4;
    const int m0 = bx * BM;

    const int a_row  = tid >> 2;
    const int a_col4 = (tid & 3) * 4;
    const int b_row  = tid >> 5;
    const int b_col4 = (tid & 31) * 4;

    float acc[TM][TN];
    #pragma unroll
    for (int i = 0; i < TM; i++)
        #pragma unroll
        for (int j = 0; j < TN; j++) acc[i][j] = 0.f;

    for (int k0 = 0; k0 < FDIM; k0 += BK) {
        #pragma unroll
        for (int r = 0; r < 2; r++) {
            int row = a_row + r * 64;
            float4 v = *(const float4*)&x[(size_t)(m0 + row) * FDIM + k0 + a_col4];
            As[a_col4 + 0][row] = v.x;
            As[a_col4 + 1][row] = v.y;
            As[a_col4 + 2][row] = v.z;
            As[a_col4 + 3][row] = v.w;
        }
        #pragma unroll
        for (int r = 0; r < 2; r++) {
            int row = b_row + r * 8;
            *(float4*)&Bs[row][b_col4] =
                *(const float4*)&W[(size_t)(k0 + row) * EDIM + e0 + b_col4];
        }
        __syncthreads();

        #pragma unroll
        for (int kk = 0; kk < BK; kk++) {
            float a[TM], b[TN];
            float4 a0 = *(const float4*)&As[kk][ty * TM];
            float4 a1 = *(const float4*)&As[kk][ty * TM + 4];
            a[0]=a0.x; a[1]=a0.y; a[2]=a0.z; a[3]=a0.w;
            a[4]=a1.x; a[5]=a1.y; a[6]=a1.z; a[7]=a1.w;
            float4 b0 = *(const float4*)&Bs[kk][tx * TN];
            float4 b1 = *(const float4*)&Bs[kk][tx * TN + 4];
            b[0]=b0.x; b[1]=b0.y; b[2]=b0.z; b[3]=b0.w;
            b[4]=b1.x; b[5]=b1.y; b[6]=b1.z; b[7]=b1.w;
            #pragma unroll
            for (int i = 0; i < TM; i++)
                #pragma unroll
                for (int j = 0; j < TN; j++)
                    acc[i][j] += a[i] * b[j];
        }
        __syncthreads();
    }

    #pragma unroll
    for (int i = 0; i < TM; i++) {
        int m = m0 + ty * TM + i;
        int b_idx = m >> 11;
        int s_idx = m & 2047;
        #pragma unroll
        for (int j = 0; j < TN; j++) {
            int e = e0 + tx * TN + j;
            float c = acc[i][j] + bias[e];
            if (which == 0) c += etype[(size_t)m * EDIM + e];
            int h = e >> 6, d = e & 63;
            size_t idx;
            if (which == 2)  // V transposed: [bh][d][s]
                idx = (((size_t)(b_idx * HEADS + h)) * DH + d) * SEQ + s_idx;
            else
                idx = (((size_t)(b_idx * HEADS + h)) * SEQ + s_idx) * DH + d;
            outbuf[idx] = c;
        }
    }
}

// ===========================================================================
// Attention. tcgen05 tf32 path (sm_103a) with 3xtf32 QK^T; fp32 fallback for
// non-'a' compile passes.
// ===========================================================================
// TMEM columns (tc path)
#define TQH 0
#define TQL 64
#define TTS 128
#define TTP 256
#define TTO 384
// SMEM offsets (dynamic)
#define SM_TMEMPTR 0
#define SM_MBAR_S  16
#define SM_MBAR_PV 24
#define SM_KEEP    64                  // 128 floats
#define SM_KH0     1024                // K_hi dims 0-31: [128k x 32 f32] SW128
#define SM_KH1     (SM_KH0 + 16384)    // K_hi dims 32-63
#define SM_KL0     (SM_KH1 + 16384)    // K_lo dims 0-31
#define SM_KL1     (SM_KL0 + 16384)    // K_lo dims 32-63
#define SM_VT      (SM_KL1 + 16384)    // 4 chunks x [64d x 32k f32] SW128
#define SM_TOTAL   (SM_VT + 32768)     // 99328

__global__ __launch_bounds__(128)
void attn_tc(const int* __restrict__ mask, float* __restrict__ out)
{
    extern __shared__ char smem[];
    const int tid = threadIdx.x;
    const int bh = blockIdx.y, b = bh >> 3, h = bh & 7;
    const int q0 = blockIdx.x * 128;

#if TC_ENABLED
    const uint32_t smem_base = smem_u32(smem);
    const int wid = tid >> 5;
    const uint32_t warpoff = (uint32_t)wid << 21;

    if (wid == 0) { TC_ALLOC(smem_base + SM_TMEMPTR, 512); TC_RELINQ(); }
    __syncthreads();
    uint32_t tmem;
    asm volatile("ld.shared.b32 %0, [%1];" : "=r"(tmem) : "r"(smem_base + SM_TMEMPTR));

    if (tid == 0) {
        MBAR_INIT(smem_base + SM_MBAR_S, 1);
        MBAR_INIT(smem_base + SM_MBAR_PV, 1);
    }

    // Q row -> TMEM hi/lo (pre-scaled by 1/sqrt(DH)); thread tid = query row tid.
    {
        const float4* qp = (const float4*)(g_q + ((size_t)bh * SEQ + q0 + tid) * DH);
        uint32_t rh[64], rl[64];
        #pragma unroll
        for (int i = 0; i < 16; i++) {
            float4 v = qp[i];
            float f[4] = { v.x * 0.125f, v.y * 0.125f, v.z * 0.125f, v.w * 0.125f };
            #pragma unroll
            for (int c = 0; c < 4; c++) {
                float hi = rna_tf32(f[c]);
                rh[i*4+c] = __float_as_uint(hi);
                rl[i*4+c] = rna_tf32_bits(f[c] - hi);
            }
        }
        TC_ST_X32(tmem + TQH + warpoff, rh);
        TC_ST_X32(tmem + TQH + 32 + warpoff, rh + 32);
        TC_ST_X32(tmem + TQL + warpoff, rl);
        TC_ST_X32(tmem + TQL + 32 + warpoff, rl + 32);
        TC_WAIT_ST();
    }
    TC_FENCE_BEFORE();
    __syncthreads();

    const uint64_t dKH0 = MKDESC(smem_base + SM_KH0);
    const uint64_t dKH1 = MKDESC(smem_base + SM_KH1);
    const uint64_t dKL0 = MKDESC(smem_base + SM_KL0);
    const uint64_t dKL1 = MKDESC(smem_base + SM_KL1);
    float* keepf = (float*)(smem + SM_KEEP);
    float lsum = 0.f;

    for (int t = 0; t < 16; t++) {
        const int kt0 = t * 128;
        if (t > 0) MBAR_WAIT(smem_base + SM_MBAR_PV, (t - 1) & 1);

        // Stage K tile [128 keys x 64 d], split hi/lo, each as 2 SW128 tiles
        const float4* kg = (const float4*)(g_k + ((size_t)bh * SEQ + kt0) * DH);
        #pragma unroll
        for (int i = 0; i < 16; i++) {
            int idx = tid + i * 128;
            int r = idx >> 4, c4 = idx & 15;
            float4 v = kg[idx];
            float4 hi, lo;
            hi.x = rna_tf32(v.x); lo.x = rna_tf32(v.x - hi.x);
            hi.y = rna_tf32(v.y); lo.y = rna_tf32(v.y - hi.y);
            hi.z = rna_tf32(v.z); lo.z = rna_tf32(v.z - hi.z);
            hi.w = rna_tf32(v.w); lo.w = rna_tf32(v.w - hi.w);
            uint32_t o = SWZ128((uint32_t)(r * 128 + (c4 & 7) * 16));
            uint32_t bh_off = (c4 & 8) ? SM_KH1 : SM_KH0;
            uint32_t bl_off = (c4 & 8) ? SM_KL1 : SM_KL0;
            *(float4*)(smem + bh_off + o) = hi;
            *(float4*)(smem + bl_off + o) = lo;
        }
        // Stage Vt tile [64 d x 128 keys] -> 4 SW128 chunks of 32 keys (RNA tf32)
        #pragma unroll
        for (int i = 0; i < 16; i++) {
            int idx = tid + i * 128;
            int d = idx >> 5, c = (idx >> 3) & 3, f = idx & 7;
            float4 v = *(const float4*)(g_v + ((size_t)bh * DH + d) * SEQ + kt0 + c * 32 + f * 4);
            v.x = rna_tf32(v.x); v.y = rna_tf32(v.y);
            v.z = rna_tf32(v.z); v.w = rna_tf32(v.w);
            *(float4*)(smem + SM_VT + c * 8192 + SWZ128((uint32_t)(d * 128 + f * 16))) = v;
        }
        keepf[tid] = (mask[b * SEQ + kt0 + tid] == 1) ? 1.f : 0.f;
        __syncthreads();

        // S = Qhi@Khi + Qlo@Khi + Qhi@Klo  (M=128, N=128, K=64 -> 8 K-steps x 3)
        if (wid == 0) {
            TC_FENCE_AFTER();
            if (elect_one()) {
                #pragma unroll
                for (int s = 0; s < 8; s++) {
                    uint64_t bh_d = (s < 4) ? (dKH0 + 2 * s) : (dKH1 + 2 * (s - 4));
                    uint64_t bl_d = (s < 4) ? (dKL0 + 2 * s) : (dKL1 + 2 * (s - 4));
                    mma_tf32_ts(tmem + TTS, tmem + TQH + 8 * s, bh_d, IDESC_S, s > 0);
                    mma_tf32_ts(tmem + TTS, tmem + TQL + 8 * s, bh_d, IDESC_S, true);
                    mma_tf32_ts(tmem + TTS, tmem + TQH + 8 * s, bl_d, IDESC_S, true);
                }
                TC_COMMIT(smem_base + SM_MBAR_S);
            }
        }
        MBAR_WAIT(smem_base + SM_MBAR_S, t & 1);
        TC_FENCE_AFTER();

        // P = keep * exp(S) (RNA tf32); row-sum; STTM into P region
        #pragma unroll
        for (int c = 0; c < 4; c++) {
            uint32_t sr[32];
            TC_LD_X32(sr, tmem + TTS + 32 * c);
            TC_WAIT_LD();
            uint32_t pr[32];
            #pragma unroll
            for (int r = 0; r < 32; r++) {
                float s = __uint_as_float(sr[r]);
                float p = keepf[32 * c + r] * __expf(s);
                lsum += p;
                pr[r] = rna_tf32_bits(p);
            }
            TC_ST_X32(tmem + TTP + 32 * c + warpoff, pr);
        }
        TC_WAIT_ST();
        TC_FENCE_BEFORE();
        __syncthreads();

        // O += P @ Vt^T  (M=128, N=64, K=128 -> 16 K-steps)
        if (wid == 0) {
            TC_FENCE_AFTER();
            if (elect_one()) {
                #pragma unroll
                for (int s = 0; s < 16; s++) {
                    uint64_t bd = MKDESC(smem_base + SM_VT + (s >> 2) * 8192) + 2 * (s & 3);
                    mma_tf32_ts(tmem + TTO, tmem + TTP + 8 * s, bd, IDESC_PV,
                                !(t == 0 && s == 0));
                }
                TC_COMMIT(smem_base + SM_MBAR_PV);
            }
        }
    }

    MBAR_WAIT(smem_base + SM_MBAR_PV, 1);   // 16th commit -> parity 1
    TC_FENCE_AFTER();

    uint32_t o0[32], o1[32];
    TC_LD_X32(o0, tmem + TTO);
    TC_LD_X32(o1, tmem + TTO + 32);
    TC_WAIT_LD();
    TC_FENCE_BEFORE();

    const int sq = q0 + tid;
    const float inv = (mask[b * SEQ + sq] == 1) ? (1.f / lsum) : 0.f;
    float* op = out + ((size_t)b * SEQ + sq) * EDIM + h * DH;
    #pragma unroll
    for (int i = 0; i < 8; i++) {
        float4 v;
        v.x = __uint_as_float(o0[i*4+0]) * inv;
        v.y = __uint_as_float(o0[i*4+1]) * inv;
        v.z = __uint_as_float(o0[i*4+2]) * inv;
        v.w = __uint_as_float(o0[i*4+3]) * inv;
        *(float4*)&op[i * 4] = v;
    }
    #pragma unroll
    for (int i = 0; i < 8; i++) {
        float4 v;
        v.x = __uint_as_float(o1[i*4+0]) * inv;
        v.y = __uint_as_float(o1[i*4+1]) * inv;
        v.z = __uint_as_float(o1[i*4+2]) * inv;
        v.w = __uint_as_float(o1[i*4+3]) * inv;
        *(float4*)&op[32 + i * 4] = v;
    }

    __syncthreads();
    if (wid == 0) TC_DEALLOC(tmem, 512);

#else  // ---------------- fp32 fallback (non-'a' compile pass) ----------------
    float* ks    = (float*)smem;              // [64][64]
    float* vs    = (float*)(smem + 16384);    // [64][64]
    float* keepf = (float*)(smem + 32768);    // 64

    const int sq = q0 + tid;
    const float* qptr = g_q + ((size_t)bh * SEQ + sq) * DH;
    float q[DH];
    #pragma unroll
    for (int d = 0; d < DH; d += 4) {
        float4 t4 = *(const float4*)&qptr[d];
        q[d+0] = t4.x * 0.125f; q[d+1] = t4.y * 0.125f;
        q[d+2] = t4.z * 0.125f; q[d+3] = t4.w * 0.125f;
    }
    float lsum = 0.f;
    float acc[DH];
    #pragma unroll
    for (int d = 0; d < DH; d++) acc[d] = 0.f;

    for (int kt0 = 0; kt0 < SEQ; kt0 += 64) {
        __syncthreads();
        const float4* kg = (const float4*)(g_k + ((size_t)bh * SEQ + kt0) * DH);
        #pragma unroll
        for (int i = 0; i < 8; i++) {
            int idx = tid + i * 128;
            ((float4*)ks)[idx] = kg[idx];
            int d = idx >> 4, f = idx & 15;   // V: transposed source
            float4 v = *(const float4*)(g_v + ((size_t)bh * DH + d) * SEQ + kt0 + f * 4);
            vs[(f*4+0)*64 + d] = v.x; vs[(f*4+1)*64 + d] = v.y;
            vs[(f*4+2)*64 + d] = v.z; vs[(f*4+3)*64 + d] = v.w;
        }
        if (tid < 64)
            keepf[tid] = (mask[b * SEQ + kt0 + tid] == 1) ? 1.f : 0.f;
        __syncthreads();

        for (int j = 0; j < 64; j++) {
            const float* kr = ks + j * 64;
            float s = 0.f;
            #pragma unroll
            for (int d = 0; d < DH; d++) s += q[d] * kr[d];
            float p = keepf[j] * __expf(s);
            lsum += p;
            const float* vr = vs + j * 64;
            #pragma unroll
            for (int d = 0; d < DH; d++) acc[d] += p * vr[d];
        }
    }
    const float inv = (mask[b * SEQ + sq] == 1) ? (1.f / lsum) : 0.f;
    float* op = out + ((size_t)b * SEQ + sq) * EDIM + h * DH;
    #pragma unroll
    for (int d = 0; d < DH; d++) op[d] = acc[d] * inv;
#endif
}

// ===========================================================================
extern "C" void kernel_launch(void* const* d_in, const int* in_sizes, int n_in,
                              void* d_out, int out_size)
{
    const float* x     = (const float*)d_in[0];
    const float* etype = (const float*)d_in[1];
    const int*   mask  = (const int*)  d_in[2];
    const float* Wq    = (const float*)d_in[3];
    const float* bq    = (const float*)d_in[4];
    const float* Wk    = (const float*)d_in[5];
    const float* bk    = (const float*)d_in[6];
    const float* Wv    = (const float*)d_in[7];
    const float* bv    = (const float*)d_in[8];
    float* out = (float*)d_out;

    dim3 ggrid(MROWS / BM, (3 * EDIM) / BN);    // 64 x 12
    qkv_gemm<<<ggrid, 256>>>(x, etype, Wq, bq, Wk, bk, Wv, bv);

    static int smem_set = 0;
    if (!smem_set) {
        cudaFuncSetAttribute(attn_tc, cudaFuncAttributeMaxDynamicSharedMemorySize, SM_TOTAL);
        smem_set = 1;
    }
    dim3 agrid(SEQ / 128, BATCH * HEADS);       // 16 x 32
    attn_tc<<<agrid, 128, SM_TOTAL>>>(mask, out);
}

// round 5
// speedup vs baseline: 3.2854x; 1.2133x over previous
#include <cuda_runtime.h>
#include <cuda_bf16.h>
#include <cstdint>

// Problem constants
#define BATCH 4
#define SEQ   2048
#define FDIM  512
#define EDIM  512
#define HEADS 8
#define DH    64
#define MROWS (BATCH*SEQ)      // 8192

// tcgen05 only exists in arch-accelerated ('a') compilation passes.
#if defined(__CUDA_ARCH_FEAT_SM103_ALL) || defined(__CUDA_ARCH_FEAT_SM100_ALL) || \
    defined(__CUDA_ARCH_SPECIFIC__) || defined(__CUDA_ARCH_FAMILY_SPECIFIC__)
#define TC_ENABLED 1
#else
#define TC_ENABLED 0
#endif

// Scratch: Q/K in [B,H,S,DH]; V stored TRANSPOSED [B,H,DH,S] for the PV MMA.
__device__ float g_q[(size_t)BATCH*HEADS*SEQ*DH];
__device__ float g_k[(size_t)BATCH*HEADS*SEQ*DH];
__device__ float g_v[(size_t)BATCH*HEADS*DH*SEQ];

// ===========================================================================
// PTX helpers
// ===========================================================================
__device__ __forceinline__ uint32_t smem_u32(const void* p) {
    uint32_t a;
    asm("{ .reg .u64 t; cvta.to.shared.u64 t, %1; cvt.u32.u64 %0, t; }" : "=r"(a) : "l"(p));
    return a;
}
__device__ __forceinline__ bool elect_one() {
    uint32_t pred;
    asm volatile("{\n\t.reg .pred p;\n\telect.sync _|p, 0xFFFFFFFF;\n\t"
                 "selp.b32 %0, 1, 0, p;\n\t}" : "=r"(pred));
    return pred != 0;
}
__device__ __forceinline__ float rna_tf32(float x) {
    uint32_t u;
    asm("cvt.rna.tf32.f32 %0, %1;" : "=r"(u) : "f"(x));
    return __uint_as_float(u);
}
__device__ __forceinline__ uint32_t rna_tf32_bits(float x) {
    uint32_t u;
    asm("cvt.rna.tf32.f32 %0, %1;" : "=r"(u) : "f"(x));
    return u;
}

#define TC_ALLOC(smem_addr, n) \
    asm volatile("tcgen05.alloc.cta_group::1.sync.aligned.shared::cta.b32 [%0], %1;" \
                 :: "r"(smem_addr), "r"((uint32_t)(n)) : "memory")
#define TC_RELINQ() \
    asm volatile("tcgen05.relinquish_alloc_permit.cta_group::1.sync.aligned;")
#define TC_DEALLOC(tmem_addr, n) \
    asm volatile("tcgen05.dealloc.cta_group::1.sync.aligned.b32 %0, %1;" \
                 :: "r"(tmem_addr), "r"((uint32_t)(n)))
#define TC_WAIT_ST() asm volatile("tcgen05.wait::st.sync.aligned;" ::: "memory")
#define TC_WAIT_LD() asm volatile("tcgen05.wait::ld.sync.aligned;" ::: "memory")
#define TC_FENCE_BEFORE() asm volatile("tcgen05.fence::before_thread_sync;" ::: "memory")
#define TC_FENCE_AFTER()  asm volatile("tcgen05.fence::after_thread_sync;" ::: "memory")
#define TC_COMMIT(mbar) \
    asm volatile("tcgen05.commit.cta_group::1.mbarrier::arrive::one.shared::cluster.b64 [%0];" \
                 :: "r"((uint32_t)(mbar)) : "memory")

#define TC_ST_X32(tmem_addr, r) \
    asm volatile("tcgen05.st.sync.aligned.32x32b.x32.b32 [%0], " \
        "{%1, %2, %3, %4, %5, %6, %7, %8, %9, %10, %11, %12, %13, %14, %15, %16, " \
        " %17, %18, %19, %20, %21, %22, %23, %24, %25, %26, %27, %28, %29, %30, %31, %32};" \
        :: "r"(tmem_addr), \
           "r"((r)[0]),"r"((r)[1]),"r"((r)[2]),"r"((r)[3]),"r"((r)[4]),"r"((r)[5]),"r"((r)[6]),"r"((r)[7]), \
           "r"((r)[8]),"r"((r)[9]),"r"((r)[10]),"r"((r)[11]),"r"((r)[12]),"r"((r)[13]),"r"((r)[14]),"r"((r)[15]), \
           "r"((r)[16]),"r"((r)[17]),"r"((r)[18]),"r"((r)[19]),"r"((r)[20]),"r"((r)[21]),"r"((r)[22]),"r"((r)[23]), \
           "r"((r)[24]),"r"((r)[25]),"r"((r)[26]),"r"((r)[27]),"r"((r)[28]),"r"((r)[29]),"r"((r)[30]),"r"((r)[31]) \
        : "memory")

#define TC_LD_X32(r, tmem_addr) \
    asm volatile("tcgen05.ld.sync.aligned.32x32b.x32.b32 " \
        "{%0, %1, %2, %3, %4, %5, %6, %7, %8, %9, %10, %11, %12, %13, %14, %15, " \
        " %16, %17, %18, %19, %20, %21, %22, %23, %24, %25, %26, %27, %28, %29, %30, %31}, [%32];" \
        : "=r"((r)[0]),"=r"((r)[1]),"=r"((r)[2]),"=r"((r)[3]),"=r"((r)[4]),"=r"((r)[5]),"=r"((r)[6]),"=r"((r)[7]), \
          "=r"((r)[8]),"=r"((r)[9]),"=r"((r)[10]),"=r"((r)[11]),"=r"((r)[12]),"=r"((r)[13]),"=r"((r)[14]),"=r"((r)[15]), \
          "=r"((r)[16]),"=r"((r)[17]),"=r"((r)[18]),"=r"((r)[19]),"=r"((r)[20]),"=r"((r)[21]),"=r"((r)[22]),"=r"((r)[23]), \
          "=r"((r)[24]),"=r"((r)[25]),"=r"((r)[26]),"=r"((r)[27]),"=r"((r)[28]),"=r"((r)[29]),"=r"((r)[30]),"=r"((r)[31]) \
        : "r"(tmem_addr))

#define MBAR_INIT(mbar, cnt) \
    asm volatile("mbarrier.init.shared.b64 [%0], %1;" :: "r"((uint32_t)(mbar)), "r"((uint32_t)(cnt)) : "memory")

#define MBAR_WAIT(mbar, parity) do { \
    uint32_t _m = (uint32_t)(mbar); uint32_t _p = (uint32_t)(parity); uint32_t _done; \
    asm volatile("{\n\t.reg .pred p;\n\t" \
        "mbarrier.try_wait.parity.acquire.cta.shared::cta.b64 p, [%1], %2;\n\t" \
        "selp.b32 %0, 1, 0, p;\n\t}" : "=r"(_done) : "r"(_m), "r"(_p) : "memory"); \
    if (!_done) { \
        asm volatile("{\n\t.reg .pred P1;\n\t" \
            "WAIT_LOOP_%=:\n\t" \
            "mbarrier.try_wait.parity.acquire.cta.shared::cta.b64 P1, [%0], %1, 0x989680;\n\t" \
            "@P1 bra.uni WAIT_DONE_%=;\n\t" \
            "bra.uni WAIT_LOOP_%=;\n\t" \
            "WAIT_DONE_%=:\n\t}" :: "r"(_m), "r"(_p) : "memory"); \
    } \
} while (0)

// SW128 SMEM descriptor (layout=2, version=1, SBO=64, LBO=1)
#define SMEM_DESC_BASE_SW128 \
    ((uint64_t(2) << 61) | (uint64_t(1) << 46) | (uint64_t(64) << 32) | (uint64_t(1) << 16))
#define MKDESC(addr) (SMEM_DESC_BASE_SW128 | ((uint64_t)((addr) >> 4) & 0x3FFF))
#define SWZ128(o) ((o) ^ (((o) >> 3) & 0x70))

#if TC_ENABLED
__device__ __forceinline__ void mma_tf32_ts(uint32_t d, uint32_t a, uint64_t bdesc,
                                            uint32_t idesc, bool acc) {
    uint32_t e = acc ? 1u : 0u;
    asm volatile("{\n\t.reg .pred p;\n\tsetp.ne.u32 p, %4, 0;\n\t"
        "tcgen05.mma.cta_group::1.kind::tf32 [%0], [%1], %2, %3, p;\n\t}"
        :: "r"(d), "r"(a), "l"(bdesc), "r"(idesc), "r"(e) : "memory");
}
#endif

// idesc: dtype=F32(1@4), atype=TF32(2@7), btype=TF32(2@10), N>>3@17, M>>4@24
// M=128, N=64 for both S and PV MMAs (K-tile = 64 keys)
#define IDESC_A ((1u<<4)|(2u<<7)|(2u<<10)|((64u/8)<<17)|((128u/16)<<24))

// ===========================================================================
// Fused QKV projection GEMM (fp32, exact — round-3 proven version).
// V epilogue stores transposed [B,H,DH,S]. etype added for Q.
// ===========================================================================
#define BM 128
#define BN 128
#define BK 16
#define TM 8
#define TN 8

__global__ __launch_bounds__(256)
void qkv_gemm(const float* __restrict__ x,
              const float* __restrict__ etype,
              const float* __restrict__ Wq, const float* __restrict__ bq,
              const float* __restrict__ Wk, const float* __restrict__ bk,
              const float* __restrict__ Wv, const float* __restrict__ bv)
{
    __shared__ float As[BK][BM];
    __shared__ float Bs[BK][BN];

    const int bx = blockIdx.x;
    const int by = blockIdx.y;
    const int n0 = by * BN;
    const int which = n0 >> 9;          // 0=q,1=k,2=v
    const int e0 = n0 & 511;

    const float* W; const float* bias; float* outbuf;
    if (which == 0)      { W = Wq; bias = bq; outbuf = g_q; }
    else if (which == 1) { W = Wk; bias = bk; outbuf = g_k; }
    else                 { W = Wv; bias = bv; outbuf = g_v; }

    const int tid = threadIdx.x;
    const int tx = tid & 15;
    const int ty = tid >> 4;
    const int m0 = bx * BM;

    const int a_row  = tid >> 2;
    const int a_col4 = (tid & 3) * 4;
    const int b_row  = tid >> 5;
    const int b_col4 = (tid & 31) * 4;

    float acc[TM][TN];
    #pragma unroll
    for (int i = 0; i < TM; i++)
        #pragma unroll
        for (int j = 0; j < TN; j++) acc[i][j] = 0.f;

    for (int k0 = 0; k0 < FDIM; k0 += BK) {
        #pragma unroll
        for (int r = 0; r < 2; r++) {
            int row = a_row + r * 64;
            float4 v = *(const float4*)&x[(size_t)(m0 + row) * FDIM + k0 + a_col4];
            As[a_col4 + 0][row] = v.x;
            As[a_col4 + 1][row] = v.y;
            As[a_col4 + 2][row] = v.z;
            As[a_col4 + 3][row] = v.w;
        }
        #pragma unroll
        for (int r = 0; r < 2; r++) {
            int row = b_row + r * 8;
            *(float4*)&Bs[row][b_col4] =
                *(const float4*)&W[(size_t)(k0 + row) * EDIM + e0 + b_col4];
        }
        __syncthreads();

        #pragma unroll
        for (int kk = 0; kk < BK; kk++) {
            float a[TM], b[TN];
            float4 a0 = *(const float4*)&As[kk][ty * TM];
            float4 a1 = *(const float4*)&As[kk][ty * TM + 4];
            a[0]=a0.x; a[1]=a0.y; a[2]=a0.z; a[3]=a0.w;
            a[4]=a1.x; a[5]=a1.y; a[6]=a1.z; a[7]=a1.w;
            float4 b0 = *(const float4*)&Bs[kk][tx * TN];
            float4 b1 = *(const float4*)&Bs[kk][tx * TN + 4];
            b[0]=b0.x; b[1]=b0.y; b[2]=b0.z; b[3]=b0.w;
            b[4]=b1.x; b[5]=b1.y; b[6]=b1.z; b[7]=b1.w;
            #pragma unroll
            for (int i = 0; i < TM; i++)
                #pragma unroll
                for (int j = 0; j < TN; j++)
                    acc[i][j] += a[i] * b[j];
        }
        __syncthreads();
    }

    #pragma unroll
    for (int i = 0; i < TM; i++) {
        int m = m0 + ty * TM + i;
        int b_idx = m >> 11;
        int s_idx = m & 2047;
        #pragma unroll
        for (int j = 0; j < TN; j++) {
            int e = e0 + tx * TN + j;
            float c = acc[i][j] + bias[e];
            if (which == 0) c += etype[(size_t)m * EDIM + e];
            int h = e >> 6, d = e & 63;
            size_t idx;
            if (which == 2)  // V transposed: [bh][d][s]
                idx = (((size_t)(b_idx * HEADS + h)) * DH + d) * SEQ + s_idx;
            else
                idx = (((size_t)(b_idx * HEADS + h)) * SEQ + s_idx) * DH + d;
            outbuf[idx] = c;
        }
    }
}

// ===========================================================================
// tcgen05 tf32x3 attention, K-tile = 64 keys, TMEM = 256 cols -> occ 2.
// TMEM: Qhi[0..63], Qlo[64..127], S/P in place [128..191], O [192..255].
// ===========================================================================
#define TQH 0
#define TQL 64
#define TSP 128
#define TTO 192
// SMEM offsets (dynamic)
#define SM_TMEMPTR 0
#define SM_MBAR_S  16
#define SM_MBAR_PV 24
#define SM_KEEP    64                  // 64 floats
#define SM_KH0     1024                // K_hi dims 0-31: [64k x 32 f32] SW128 (8KB)
#define SM_KH1     (SM_KH0 + 8192)
#define SM_KL0     (SM_KH1 + 8192)
#define SM_KL1     (SM_KL0 + 8192)
#define SM_VT      (SM_KL1 + 8192)     // 2 chunks x [64d x 32k f32] = 16KB
#define SM_TOTAL   (SM_VT + 16384)     // 50176

__global__ __launch_bounds__(128)
void attn_tc(const int* __restrict__ mask, float* __restrict__ out)
{
    extern __shared__ char smem[];
    const int tid = threadIdx.x;
    const int bh = blockIdx.y, b = bh >> 3, h = bh & 7;
    const int q0 = blockIdx.x * 128;

#if TC_ENABLED
    const uint32_t smem_base = smem_u32(smem);
    const int wid = tid >> 5;
    const uint32_t warpoff = (uint32_t)wid << 21;

    if (wid == 0) { TC_ALLOC(smem_base + SM_TMEMPTR, 256); TC_RELINQ(); }
    __syncthreads();
    uint32_t tmem;
    asm volatile("ld.shared.b32 %0, [%1];" : "=r"(tmem) : "r"(smem_base + SM_TMEMPTR));

    if (tid == 0) {
        MBAR_INIT(smem_base + SM_MBAR_S, 1);
        MBAR_INIT(smem_base + SM_MBAR_PV, 1);
    }

    // Q row -> TMEM hi/lo (pre-scaled by 1/sqrt(DH)); thread tid = query row tid.
    {
        const float4* qp = (const float4*)(g_q + ((size_t)bh * SEQ + q0 + tid) * DH);
        uint32_t rh[64], rl[64];
        #pragma unroll
        for (int i = 0; i < 16; i++) {
            float4 v = qp[i];
            float f[4] = { v.x * 0.125f, v.y * 0.125f, v.z * 0.125f, v.w * 0.125f };
            #pragma unroll
            for (int c = 0; c < 4; c++) {
                float hi = rna_tf32(f[c]);
                rh[i*4+c] = __float_as_uint(hi);
                rl[i*4+c] = rna_tf32_bits(f[c] - hi);
            }
        }
        TC_ST_X32(tmem + TQH + warpoff, rh);
        TC_ST_X32(tmem + TQH + 32 + warpoff, rh + 32);
        TC_ST_X32(tmem + TQL + warpoff, rl);
        TC_ST_X32(tmem + TQL + 32 + warpoff, rl + 32);
        TC_WAIT_ST();
    }
    TC_FENCE_BEFORE();
    __syncthreads();

    const uint64_t dKH0 = MKDESC(smem_base + SM_KH0);
    const uint64_t dKH1 = MKDESC(smem_base + SM_KH1);
    const uint64_t dKL0 = MKDESC(smem_base + SM_KL0);
    const uint64_t dKL1 = MKDESC(smem_base + SM_KL1);
    float* keepf = (float*)(smem + SM_KEEP);
    float lsum = 0.f;

    for (int t = 0; t < 32; t++) {
        const int kt0 = t * 64;
        // PV(t-1) completion also protects the in-place S/P region (TSP).
        if (t > 0) MBAR_WAIT(smem_base + SM_MBAR_PV, (t - 1) & 1);

        // Stage K tile [64 keys x 64 d], split hi/lo, each as 2 SW128 buffers
        const float4* kg = (const float4*)(g_k + ((size_t)bh * SEQ + kt0) * DH);
        #pragma unroll
        for (int i = 0; i < 8; i++) {
            int idx = tid + i * 128;
            int r = idx >> 4, c4 = idx & 15;
            float4 v = kg[idx];
            float4 hi, lo;
            hi.x = rna_tf32(v.x); lo.x = rna_tf32(v.x - hi.x);
            hi.y = rna_tf32(v.y); lo.y = rna_tf32(v.y - hi.y);
            hi.z = rna_tf32(v.z); lo.z = rna_tf32(v.z - hi.z);
            hi.w = rna_tf32(v.w); lo.w = rna_tf32(v.w - hi.w);
            uint32_t o = SWZ128((uint32_t)(r * 128 + (c4 & 7) * 16));
            uint32_t bh_off = (c4 & 8) ? SM_KH1 : SM_KH0;
            uint32_t bl_off = (c4 & 8) ? SM_KL1 : SM_KL0;
            *(float4*)(smem + bh_off + o) = hi;
            *(float4*)(smem + bl_off + o) = lo;
        }
        // Stage Vt tile [64 d x 64 keys] -> 2 SW128 chunks of 32 keys (RNA tf32)
        #pragma unroll
        for (int i = 0; i < 8; i++) {
            int idx = tid + i * 128;
            int d = idx >> 4, kc = idx & 15;
            int c = kc >> 3, f = kc & 7;
            float4 v = *(const float4*)(g_v + ((size_t)bh * DH + d) * SEQ + kt0 + c * 32 + f * 4);
            v.x = rna_tf32(v.x); v.y = rna_tf32(v.y);
            v.z = rna_tf32(v.z); v.w = rna_tf32(v.w);
            *(float4*)(smem + SM_VT + c * 8192 + SWZ128((uint32_t)(d * 128 + f * 16))) = v;
        }
        if (tid < 64)
            keepf[tid] = (mask[b * SEQ + kt0 + tid] == 1) ? 1.f : 0.f;
        __syncthreads();

        // S = Qhi@Khi + Qlo@Khi + Qhi@Klo  (M=128, N=64, K=64 -> 8 K-steps x 3)
        if (wid == 0) {
            TC_FENCE_AFTER();
            if (elect_one()) {
                #pragma unroll
                for (int s = 0; s < 8; s++) {
                    uint64_t bh_d = (s < 4) ? (dKH0 + 2 * s) : (dKH1 + 2 * (s - 4));
                    uint64_t bl_d = (s < 4) ? (dKL0 + 2 * s) : (dKL1 + 2 * (s - 4));
                    mma_tf32_ts(tmem + TSP, tmem + TQH + 8 * s, bh_d, IDESC_A, s > 0);
                    mma_tf32_ts(tmem + TSP, tmem + TQL + 8 * s, bh_d, IDESC_A, true);
                    mma_tf32_ts(tmem + TSP, tmem + TQH + 8 * s, bl_d, IDESC_A, true);
                }
                TC_COMMIT(smem_base + SM_MBAR_S);
            }
        }
        MBAR_WAIT(smem_base + SM_MBAR_S, t & 1);
        TC_FENCE_AFTER();

        // P = keep * exp(S), in place (each warp touches only its own lanes)
        #pragma unroll
        for (int c = 0; c < 2; c++) {
            uint32_t sr[32];
            TC_LD_X32(sr, tmem + TSP + 32 * c);
            TC_WAIT_LD();
            uint32_t pr[32];
            #pragma unroll
            for (int r = 0; r < 32; r++) {
                float s = __uint_as_float(sr[r]);
                float p = keepf[32 * c + r] * __expf(s);
                lsum += p;
                pr[r] = rna_tf32_bits(p);
            }
            TC_ST_X32(tmem + TSP + 32 * c + warpoff, pr);
        }
        TC_WAIT_ST();
        TC_FENCE_BEFORE();
        __syncthreads();

        // O += P @ Vt^T  (M=128, N=64, K=64 -> 8 K-steps)
        if (wid == 0) {
            TC_FENCE_AFTER();
            if (elect_one()) {
                #pragma unroll
                for (int s = 0; s < 8; s++) {
                    uint64_t bd = MKDESC(smem_base + SM_VT + (s >> 2) * 8192) + 2 * (s & 3);
                    mma_tf32_ts(tmem + TTO, tmem + TSP + 8 * s, bd, IDESC_A,
                                !(t == 0 && s == 0));
                }
                TC_COMMIT(smem_base + SM_MBAR_PV);
            }
        }
    }

    MBAR_WAIT(smem_base + SM_MBAR_PV, 1);   // 32nd commit -> parity 31&1 = 1
    TC_FENCE_AFTER();

    uint32_t o0[32], o1[32];
    TC_LD_X32(o0, tmem + TTO);
    TC_LD_X32(o1, tmem + TTO + 32);
    TC_WAIT_LD();
    TC_FENCE_BEFORE();

    const int sq = q0 + tid;
    const float inv = (mask[b * SEQ + sq] == 1) ? (1.f / lsum) : 0.f;
    float* op = out + ((size_t)b * SEQ + sq) * EDIM + h * DH;
    #pragma unroll
    for (int i = 0; i < 8; i++) {
        float4 v;
        v.x = __uint_as_float(o0[i*4+0]) * inv;
        v.y = __uint_as_float(o0[i*4+1]) * inv;
        v.z = __uint_as_float(o0[i*4+2]) * inv;
        v.w = __uint_as_float(o0[i*4+3]) * inv;
        *(float4*)&op[i * 4] = v;
    }
    #pragma unroll
    for (int i = 0; i < 8; i++) {
        float4 v;
        v.x = __uint_as_float(o1[i*4+0]) * inv;
        v.y = __uint_as_float(o1[i*4+1]) * inv;
        v.z = __uint_as_float(o1[i*4+2]) * inv;
        v.w = __uint_as_float(o1[i*4+3]) * inv;
        *(float4*)&op[32 + i * 4] = v;
    }

    __syncthreads();
    if (wid == 0) TC_DEALLOC(tmem, 256);

#else  // ---------------- fp32 fallback (non-'a' compile pass) ----------------
    float* ks    = (float*)smem;              // [64][64]
    float* vs    = (float*)(smem + 16384);    // [64][64]
    float* keepf = (float*)(smem + 32768);    // 64

    const int sq = q0 + tid;
    const float* qptr = g_q + ((size_t)bh * SEQ + sq) * DH;
    float q[DH];
    #pragma unroll
    for (int d = 0; d < DH; d += 4) {
        float4 t4 = *(const float4*)&qptr[d];
        q[d+0] = t4.x * 0.125f; q[d+1] = t4.y * 0.125f;
        q[d+2] = t4.z * 0.125f; q[d+3] = t4.w * 0.125f;
    }
    float lsum = 0.f;
    float acc[DH];
    #pragma unroll
    for (int d = 0; d < DH; d++) acc[d] = 0.f;

    for (int kt0 = 0; kt0 < SEQ; kt0 += 64) {
        __syncthreads();
        const float4* kg = (const float4*)(g_k + ((size_t)bh * SEQ + kt0) * DH);
        #pragma unroll
        for (int i = 0; i < 8; i++) {
            int idx = tid + i * 128;
            ((float4*)ks)[idx] = kg[idx];
            int d = idx >> 4, f = idx & 15;   // V: transposed source
            float4 v = *(const float4*)(g_v + ((size_t)bh * DH + d) * SEQ + kt0 + f * 4);
            vs[(f*4+0)*64 + d] = v.x; vs[(f*4+1)*64 + d] = v.y;
            vs[(f*4+2)*64 + d] = v.z; vs[(f*4+3)*64 + d] = v.w;
        }
        if (tid < 64)
            keepf[tid] = (mask[b * SEQ + kt0 + tid] == 1) ? 1.f : 0.f;
        __syncthreads();

        for (int j = 0; j < 64; j++) {
            const float* kr = ks + j * 64;
            float s = 0.f;
            #pragma unroll
            for (int d = 0; d < DH; d++) s += q[d] * kr[d];
            float p = keepf[j] * __expf(s);
            lsum += p;
            const float* vr = vs + j * 64;
            #pragma unroll
            for (int d = 0; d < DH; d++) acc[d] += p * vr[d];
        }
    }
    const float inv = (mask[b * SEQ + sq] == 1) ? (1.f / lsum) : 0.f;
    float* op = out + ((size_t)b * SEQ + sq) * EDIM + h * DH;
    #pragma unroll
    for (int d = 0; d < DH; d++) op[d] = acc[d] * inv;
#endif
}

// ===========================================================================
extern "C" void kernel_launch(void* const* d_in, const int* in_sizes, int n_in,
                              void* d_out, int out_size)
{
    const float* x     = (const float*)d_in[0];
    const float* etype = (const float*)d_in[1];
    const int*   mask  = (const int*)  d_in[2];
    const float* Wq    = (const float*)d_in[3];
    const float* bq    = (const float*)d_in[4];
    const float* Wk    = (const float*)d_in[5];
    const float* bk    = (const float*)d_in[6];
    const float* Wv    = (const float*)d_in[7];
    const float* bv    = (const float*)d_in[8];
    float* out = (float*)d_out;

    dim3 ggrid(MROWS / BM, (3 * EDIM) / BN);    // 64 x 12
    qkv_gemm<<<ggrid, 256>>>(x, etype, Wq, bq, Wk, bk, Wv, bv);

    static int smem_set = 0;
    if (!smem_set) {
        cudaFuncSetAttribute(attn_tc, cudaFuncAttributeMaxDynamicSharedMemorySize, SM_TOTAL);
        smem_set = 1;
    }
    dim3 agrid(SEQ / 128, BATCH * HEADS);       // 16 x 32
    attn_tc<<<agrid, 128, SM_TOTAL>>>(mask, out);
}

// round 8
// speedup vs baseline: 5.4830x; 1.6689x over previous
#include <cuda_runtime.h>
#include <cuda_bf16.h>
#include <cstdint>

// Problem constants
#define BATCH 4
#define SEQ   2048
#define FDIM  512
#define EDIM  512
#define HEADS 8
#define DH    64
#define MROWS (BATCH*SEQ)      // 8192

// tcgen05 only exists in arch-accelerated ('a') compilation passes.
#if defined(__CUDA_ARCH_FEAT_SM103_ALL) || defined(__CUDA_ARCH_FEAT_SM100_ALL) || \
    defined(__CUDA_ARCH_SPECIFIC__) || defined(__CUDA_ARCH_FAMILY_SPECIFIC__)
#define TC_ENABLED 1
#else
#define TC_ENABLED 0
#endif

// Scratch: Q/K in [B,H,S,DH]; V stored TRANSPOSED [B,H,DH,S] for the PV MMA.
__device__ float g_q[(size_t)BATCH*HEADS*SEQ*DH];
__device__ float g_k[(size_t)BATCH*HEADS*SEQ*DH];
__device__ float g_v[(size_t)BATCH*HEADS*DH*SEQ];
// W^T concat [1536 n][512 k] fp32 (Wq^T | Wk^T | Wv^T), written by cvt_wt.
__device__ float g_wt[(size_t)3*EDIM*FDIM];

// ===========================================================================
// PTX helpers
// ===========================================================================
__device__ __forceinline__ uint32_t smem_u32(const void* p) {
    uint32_t a;
    asm("{ .reg .u64 t; cvta.to.shared.u64 t, %1; cvt.u32.u64 %0, t; }" : "=r"(a) : "l"(p));
    return a;
}
__device__ __forceinline__ bool elect_one() {
    uint32_t pred;
    asm volatile("{\n\t.reg .pred p;\n\telect.sync _|p, 0xFFFFFFFF;\n\t"
                 "selp.b32 %0, 1, 0, p;\n\t}" : "=r"(pred));
    return pred != 0;
}
__device__ __forceinline__ float rna_tf32(float x) {
    uint32_t u;
    asm("cvt.rna.tf32.f32 %0, %1;" : "=r"(u) : "f"(x));
    return __uint_as_float(u);
}
__device__ __forceinline__ uint32_t rna_tf32_bits(float x) {
    uint32_t u;
    asm("cvt.rna.tf32.f32 %0, %1;" : "=r"(u) : "f"(x));
    return u;
}

#define TC_ALLOC(smem_addr, n) \
    asm volatile("tcgen05.alloc.cta_group::1.sync.aligned.shared::cta.b32 [%0], %1;" \
                 :: "r"(smem_addr), "r"((uint32_t)(n)) : "memory")
#define TC_RELINQ() \
    asm volatile("tcgen05.relinquish_alloc_permit.cta_group::1.sync.aligned;")
#define TC_DEALLOC(tmem_addr, n) \
    asm volatile("tcgen05.dealloc.cta_group::1.sync.aligned.b32 %0, %1;" \
                 :: "r"(tmem_addr), "r"((uint32_t)(n)))
#define TC_WAIT_ST() asm volatile("tcgen05.wait::st.sync.aligned;" ::: "memory")
#define TC_WAIT_LD() asm volatile("tcgen05.wait::ld.sync.aligned;" ::: "memory")
#define TC_FENCE_BEFORE() asm volatile("tcgen05.fence::before_thread_sync;" ::: "memory")
#define TC_FENCE_AFTER()  asm volatile("tcgen05.fence::after_thread_sync;" ::: "memory")
#define TC_COMMIT(mbar) \
    asm volatile("tcgen05.commit.cta_group::1.mbarrier::arrive::one.shared::cluster.b64 [%0];" \
                 :: "r"((uint32_t)(mbar)) : "memory")

#define TC_ST_X32(tmem_addr, r) \
    asm volatile("tcgen05.st.sync.aligned.32x32b.x32.b32 [%0], " \
        "{%1, %2, %3, %4, %5, %6, %7, %8, %9, %10, %11, %12, %13, %14, %15, %16, " \
        " %17, %18, %19, %20, %21, %22, %23, %24, %25, %26, %27, %28, %29, %30, %31, %32};" \
        :: "r"(tmem_addr), \
           "r"((r)[0]),"r"((r)[1]),"r"((r)[2]),"r"((r)[3]),"r"((r)[4]),"r"((r)[5]),"r"((r)[6]),"r"((r)[7]), \
           "r"((r)[8]),"r"((r)[9]),"r"((r)[10]),"r"((r)[11]),"r"((r)[12]),"r"((r)[13]),"r"((r)[14]),"r"((r)[15]), \
           "r"((r)[16]),"r"((r)[17]),"r"((r)[18]),"r"((r)[19]),"r"((r)[20]),"r"((r)[21]),"r"((r)[22]),"r"((r)[23]), \
           "r"((r)[24]),"r"((r)[25]),"r"((r)[26]),"r"((r)[27]),"r"((r)[28]),"r"((r)[29]),"r"((r)[30]),"r"((r)[31]) \
        : "memory")

#define TC_LD_X32(r, tmem_addr) \
    asm volatile("tcgen05.ld.sync.aligned.32x32b.x32.b32 " \
        "{%0, %1, %2, %3, %4, %5, %6, %7, %8, %9, %10, %11, %12, %13, %14, %15, " \
        " %16, %17, %18, %19, %20, %21, %22, %23, %24, %25, %26, %27, %28, %29, %30, %31}, [%32];" \
        : "=r"((r)[0]),"=r"((r)[1]),"=r"((r)[2]),"=r"((r)[3]),"=r"((r)[4]),"=r"((r)[5]),"=r"((r)[6]),"=r"((r)[7]), \
          "=r"((r)[8]),"=r"((r)[9]),"=r"((r)[10]),"=r"((r)[11]),"=r"((r)[12]),"=r"((r)[13]),"=r"((r)[14]),"=r"((r)[15]), \
          "=r"((r)[16]),"=r"((r)[17]),"=r"((r)[18]),"=r"((r)[19]),"=r"((r)[20]),"=r"((r)[21]),"=r"((r)[22]),"=r"((r)[23]), \
          "=r"((r)[24]),"=r"((r)[25]),"=r"((r)[26]),"=r"((r)[27]),"=r"((r)[28]),"=r"((r)[29]),"=r"((r)[30]),"=r"((r)[31]) \
        : "r"(tmem_addr))

#define MBAR_INIT(mbar, cnt) \
    asm volatile("mbarrier.init.shared.b64 [%0], %1;" :: "r"((uint32_t)(mbar)), "r"((uint32_t)(cnt)) : "memory")

#define MBAR_WAIT(mbar, parity) do { \
    uint32_t _m = (uint32_t)(mbar); uint32_t _p = (uint32_t)(parity); uint32_t _done; \
    asm volatile("{\n\t.reg .pred p;\n\t" \
        "mbarrier.try_wait.parity.acquire.cta.shared::cta.b64 p, [%1], %2;\n\t" \
        "selp.b32 %0, 1, 0, p;\n\t}" : "=r"(_done) : "r"(_m), "r"(_p) : "memory"); \
    if (!_done) { \
        asm volatile("{\n\t.reg .pred P1;\n\t" \
            "WAIT_LOOP_%=:\n\t" \
            "mbarrier.try_wait.parity.acquire.cta.shared::cta.b64 P1, [%0], %1, 0x989680;\n\t" \
            "@P1 bra.uni WAIT_DONE_%=;\n\t" \
            "bra.uni WAIT_LOOP_%=;\n\t" \
            "WAIT_DONE_%=:\n\t}" :: "r"(_m), "r"(_p) : "memory"); \
    } \
} while (0)

// SW128 SMEM descriptor (layout=2, version=1, SBO=64, LBO=1)
#define SMEM_DESC_BASE_SW128 \
    ((uint64_t(2) << 61) | (uint64_t(1) << 46) | (uint64_t(64) << 32) | (uint64_t(1) << 16))
#define MKDESC(addr) (SMEM_DESC_BASE_SW128 | ((uint64_t)((addr) >> 4) & 0x3FFF))
#define SWZ128(o) ((o) ^ (((o) >> 3) & 0x70))

#if TC_ENABLED
__device__ __forceinline__ void mma_tf32_ts(uint32_t d, uint32_t a, uint64_t bdesc,
                                            uint32_t idesc, bool acc) {
    uint32_t e = acc ? 1u : 0u;
    asm volatile("{\n\t.reg .pred p;\n\tsetp.ne.u32 p, %4, 0;\n\t"
        "tcgen05.mma.cta_group::1.kind::tf32 [%0], [%1], %2, %3, p;\n\t}"
        :: "r"(d), "r"(a), "l"(bdesc), "r"(idesc), "r"(e) : "memory");
}
#endif

// idesc: dtype=F32(1@4), atype=TF32(2@7), btype=TF32(2@10), N>>3@17, M>>4@24
// M=128, N=64 — the exact constant proven in the round-5 attention kernel.
#define IDESC_A ((1u<<4)|(2u<<7)|(2u<<10)|((64u/8)<<17)|((128u/16)<<24))

// ===========================================================================
// cvt_wt: W [512k x 512n] -> g_wt [n][k], rows concat over q/k/v.
// Padded 32x32 SMEM transpose; coalesced both directions.
// ===========================================================================
__global__ __launch_bounds__(256)
void cvt_wt(const float* __restrict__ Wq, const float* __restrict__ Wk,
            const float* __restrict__ Wv)
{
    __shared__ float t[32][33];
    const int z = blockIdx.z;
    const float* W = (z == 0) ? Wq : (z == 1) ? Wk : Wv;
    const int k0 = blockIdx.x * 32;
    const int n0 = blockIdx.y * 32;
    const int tx = threadIdx.x & 31;
    const int ty = threadIdx.x >> 5;          // 0..7
    #pragma unroll
    for (int i = 0; i < 4; i++)
        t[ty + 8*i][tx] = W[(size_t)(k0 + ty + 8*i) * EDIM + n0 + tx];
    __syncthreads();
    #pragma unroll
    for (int i = 0; i < 4; i++)
        g_wt[(size_t)(z * EDIM + n0 + ty + 8*i) * FDIM + k0 + tx] = t[tx][ty + 8*i];
}

// ===========================================================================
// tcgen05 tf32x3 projection GEMM — clone of the PROVEN attention S-MMA:
//   A (TMEM) = x rows [128m x 64k] hi/lo   (Q-load pattern, thread=row)
//   B (SMEM) = W^T tile [64n x 64k] hi/lo  (K-staging pattern, from g_wt)
//   D [128m x 64n] fp32, accumulated over 8 serialized k-chunks.
// One CTA = 128 m-rows x 64 n-features (one head's worth).
// TMEM: Xh[0..63], Xl[64..127], D[128..191]. alloc 256 -> occ 2.
// ===========================================================================
#define TXH 0
#define TXL 64
#define TD  128
#define GT_TMEMPTR 0
#define GT_MBAR    16
#define GT_BIAS    64                  // 64 floats
#define GT_WH0     1024                // W^T hi k 0-31: [64n x 32k f32] SW128 8KB
#define GT_WH1     (GT_WH0 + 8192)
#define GT_WL0     (GT_WH1 + 8192)
#define GT_WL1     (GT_WL0 + 8192)
#define GT_TOTAL   (GT_WL1 + 8192)     // 33792

__global__ __launch_bounds__(128)
void tc_gemm(const float* __restrict__ x,
             const float* __restrict__ etype,
             const float* __restrict__ bq, const float* __restrict__ bk,
             const float* __restrict__ bv)
{
    extern __shared__ char sm[];
    const int tid = threadIdx.x;
    const int m0 = blockIdx.x * 128;
    const int n0g = blockIdx.y * 64;    // over 1536
    const int which = n0g >> 9;         // 0=q,1=k,2=v
    const int e0 = n0g & 511;           // multiple of 64 -> single head
    const int hh = e0 >> 6;
    const float* bias = (which == 0) ? bq : (which == 1) ? bk : bv;

#if TC_ENABLED
    const uint32_t base = smem_u32(sm);
    const int wid = tid >> 5;
    const uint32_t warpoff = (uint32_t)wid << 21;

    if (wid == 0) { TC_ALLOC(base + GT_TMEMPTR, 256); TC_RELINQ(); }
    __syncthreads();
    uint32_t tmem;
    asm volatile("ld.shared.b32 %0, [%1];" : "=r"(tmem) : "r"(base + GT_TMEMPTR));
    if (tid == 0) MBAR_INIT(base + GT_MBAR, 1);
    if (tid < 64) ((float*)(sm + GT_BIAS))[tid] = bias[e0 + tid];
    __syncthreads();

    const uint64_t dWH0 = MKDESC(base + GT_WH0);
    const uint64_t dWH1 = MKDESC(base + GT_WH1);
    const uint64_t dWL0 = MKDESC(base + GT_WL0);
    const uint64_t dWL1 = MKDESC(base + GT_WL1);

    for (int c = 0; c < 8; c++) {
        const int k0 = c * 64;

        // --- Stage W^T tile [64n x 64k] hi/lo (attention K-staging clone) ---
        #pragma unroll
        for (int i = 0; i < 8; i++) {
            int idx = tid + i * 128;            // 1024 float4
            int r = idx >> 4, c4 = idx & 15;
            float4 v = *(const float4*)&g_wt[(size_t)(n0g + r) * FDIM + k0 + c4 * 4];
            float4 hi, lo;
            hi.x = rna_tf32(v.x); lo.x = rna_tf32(v.x - hi.x);
            hi.y = rna_tf32(v.y); lo.y = rna_tf32(v.y - hi.y);
            hi.z = rna_tf32(v.z); lo.z = rna_tf32(v.z - hi.z);
            hi.w = rna_tf32(v.w); lo.w = rna_tf32(v.w - hi.w);
            uint32_t o = SWZ128((uint32_t)(r * 128 + (c4 & 7) * 16));
            uint32_t bh_off = (c4 & 8) ? GT_WH1 : GT_WH0;
            uint32_t bl_off = (c4 & 8) ? GT_WL1 : GT_WL0;
            *(float4*)(sm + bh_off + o) = hi;
            *(float4*)(sm + bl_off + o) = lo;
        }

        // --- x chunk -> TMEM hi/lo (attention Q-load clone; thread = row) ---
        {
            const float4* xp = (const float4*)(x + (size_t)(m0 + tid) * FDIM + k0);
            uint32_t rh[64], rl[64];
            #pragma unroll
            for (int i = 0; i < 16; i++) {
                float4 v = xp[i];
                float f[4] = { v.x, v.y, v.z, v.w };
                #pragma unroll
                for (int cc = 0; cc < 4; cc++) {
                    float hi = rna_tf32(f[cc]);
                    rh[i*4+cc] = __float_as_uint(hi);
                    rl[i*4+cc] = rna_tf32_bits(f[cc] - hi);
                }
            }
            TC_ST_X32(tmem + TXH + warpoff, rh);
            TC_ST_X32(tmem + TXH + 32 + warpoff, rh + 32);
            TC_ST_X32(tmem + TXL + warpoff, rl);
            TC_ST_X32(tmem + TXL + 32 + warpoff, rl + 32);
            TC_WAIT_ST();
        }
        TC_FENCE_BEFORE();
        __syncthreads();

        // --- D += Xh@Wh + Xl@Wh + Xh@Wl  (8 K-steps of K=8 tf32) ---
        if (wid == 0) {
            TC_FENCE_AFTER();
            if (elect_one()) {
                #pragma unroll
                for (int s = 0; s < 8; s++) {
                    uint64_t bh_d = (s < 4) ? (dWH0 + 2 * s) : (dWH1 + 2 * (s - 4));
                    uint64_t bl_d = (s < 4) ? (dWL0 + 2 * s) : (dWL1 + 2 * (s - 4));
                    mma_tf32_ts(tmem + TD, tmem + TXH + 8 * s, bh_d, IDESC_A,
                                !(c == 0 && s == 0));
                    mma_tf32_ts(tmem + TD, tmem + TXL + 8 * s, bh_d, IDESC_A, true);
                    mma_tf32_ts(tmem + TD, tmem + TXH + 8 * s, bl_d, IDESC_A, true);
                }
                TC_COMMIT(base + GT_MBAR);
            }
        }
        // SERIALIZE: all threads wait for this chunk before restaging.
        MBAR_WAIT(base + GT_MBAR, c & 1);
        TC_FENCE_AFTER();
        __syncthreads();
    }

    // --- Epilogue: thread tid owns D row m = tid (x row m0+tid) ---
    uint32_t d0[32], d1[32];
    TC_LD_X32(d0, tmem + TD);
    TC_LD_X32(d1, tmem + TD + 32);
    TC_WAIT_LD();
    TC_FENCE_BEFORE();

    const int bb = m0 >> 11;
    const int sidx = (m0 & 2047) + tid;
    const float* bs = (const float*)(sm + GT_BIAS);

    if (which != 2) {
        float* outbuf = (which == 0) ? g_q : g_k;
        float* rowp = outbuf + ((size_t)(bb * HEADS + hh) * SEQ + sidx) * DH;
        const float* ep = (which == 0)
            ? etype + (size_t)(m0 + tid) * EDIM + e0 : nullptr;
        #pragma unroll
        for (int n4 = 0; n4 < 16; n4++) {
            const uint32_t* dr = (n4 < 8) ? d0 : d1;
            int j = (n4 & 7) * 4;
            float4 v;
            v.x = __uint_as_float(dr[j+0]) + bs[n4*4+0];
            v.y = __uint_as_float(dr[j+1]) + bs[n4*4+1];
            v.z = __uint_as_float(dr[j+2]) + bs[n4*4+2];
            v.w = __uint_as_float(dr[j+3]) + bs[n4*4+3];
            if (which == 0) {
                float4 e4 = *(const float4*)&ep[n4*4];
                v.x += e4.x; v.y += e4.y; v.z += e4.z; v.w += e4.w;
            }
            *(float4*)&rowp[n4*4] = v;
        }
    } else {
        // V transposed [bh][d][s]: per column n, lanes -> consecutive s (coalesced)
        float* vb = g_v + ((size_t)(bb * HEADS + hh) * DH) * SEQ + sidx;
        #pragma unroll
        for (int n = 0; n < 32; n++)
            vb[(size_t)n * SEQ] = __uint_as_float(d0[n]) + bs[n];
        #pragma unroll
        for (int n = 0; n < 32; n++)
            vb[(size_t)(n + 32) * SEQ] = __uint_as_float(d1[n]) + bs[n + 32];
    }
    __syncthreads();
    if (wid == 0) TC_DEALLOC(tmem, 256);

#else  // ------------- fp32 fallback GEMM (non-'a' compile pass) -------------
    // Thread tid = x row m0+tid; 64 outputs via g_wt rows (correct, not fast).
    const int bb = m0 >> 11;
    const int sidx = (m0 & 2047) + tid;
    float acc[64];
    #pragma unroll
    for (int n = 0; n < 64; n++) acc[n] = 0.f;
    for (int k = 0; k < FDIM; k++) {
        float a = x[(size_t)(m0 + tid) * FDIM + k];
        #pragma unroll 16
        for (int n = 0; n < 64; n++)
            acc[n] += a * g_wt[(size_t)(n0g + n) * FDIM + k];
    }
    if (which != 2) {
        float* outbuf = (which == 0) ? g_q : g_k;
        float* rowp = outbuf + ((size_t)(bb * HEADS + hh) * SEQ + sidx) * DH;
        for (int n = 0; n < 64; n++) {
            float v = acc[n] + bias[e0 + n];
            if (which == 0) v += etype[(size_t)(m0 + tid) * EDIM + e0 + n];
            rowp[n] = v;
        }
    } else {
        float* vb = g_v + ((size_t)(bb * HEADS + hh) * DH) * SEQ + sidx;
        for (int n = 0; n < 64; n++)
            vb[(size_t)n * SEQ] = acc[n] + bias[e0 + n];
    }
#endif
}

// ===========================================================================
// tcgen05 tf32x3 attention (round-5 proven, byte-identical).
// TMEM: Qhi[0..63], Qlo[64..127], S/P in place [128..191], O [192..255].
// ===========================================================================
#define TQH 0
#define TQL 64
#define TSP 128
#define TTO 192
#define SM_TMEMPTR 0
#define SM_MBAR_S  16
#define SM_MBAR_PV 24
#define SM_KEEP    64
#define SM_KH0     1024
#define SM_KH1     (SM_KH0 + 8192)
#define SM_KL0     (SM_KH1 + 8192)
#define SM_KL1     (SM_KL0 + 8192)
#define SM_VT      (SM_KL1 + 8192)
#define SM_TOTAL   (SM_VT + 16384)     // 50176

__global__ __launch_bounds__(128)
void attn_tc(const int* __restrict__ mask, float* __restrict__ out)
{
    extern __shared__ char smem[];
    const int tid = threadIdx.x;
    const int bh = blockIdx.y, b = bh >> 3, h = bh & 7;
    const int q0 = blockIdx.x * 128;

#if TC_ENABLED
    const uint32_t smem_base = smem_u32(smem);
    const int wid = tid >> 5;
    const uint32_t warpoff = (uint32_t)wid << 21;

    if (wid == 0) { TC_ALLOC(smem_base + SM_TMEMPTR, 256); TC_RELINQ(); }
    __syncthreads();
    uint32_t tmem;
    asm volatile("ld.shared.b32 %0, [%1];" : "=r"(tmem) : "r"(smem_base + SM_TMEMPTR));

    if (tid == 0) {
        MBAR_INIT(smem_base + SM_MBAR_S, 1);
        MBAR_INIT(smem_base + SM_MBAR_PV, 1);
    }

    {
        const float4* qp = (const float4*)(g_q + ((size_t)bh * SEQ + q0 + tid) * DH);
        uint32_t rh[64], rl[64];
        #pragma unroll
        for (int i = 0; i < 16; i++) {
            float4 v = qp[i];
            float f[4] = { v.x * 0.125f, v.y * 0.125f, v.z * 0.125f, v.w * 0.125f };
            #pragma unroll
            for (int c = 0; c < 4; c++) {
                float hi = rna_tf32(f[c]);
                rh[i*4+c] = __float_as_uint(hi);
                rl[i*4+c] = rna_tf32_bits(f[c] - hi);
            }
        }
        TC_ST_X32(tmem + TQH + warpoff, rh);
        TC_ST_X32(tmem + TQH + 32 + warpoff, rh + 32);
        TC_ST_X32(tmem + TQL + warpoff, rl);
        TC_ST_X32(tmem + TQL + 32 + warpoff, rl + 32);
        TC_WAIT_ST();
    }
    TC_FENCE_BEFORE();
    __syncthreads();

    const uint64_t dKH0 = MKDESC(smem_base + SM_KH0);
    const uint64_t dKH1 = MKDESC(smem_base + SM_KH1);
    const uint64_t dKL0 = MKDESC(smem_base + SM_KL0);
    const uint64_t dKL1 = MKDESC(smem_base + SM_KL1);
    float* keepf = (float*)(smem + SM_KEEP);
    float lsum = 0.f;

    for (int t = 0; t < 32; t++) {
        const int kt0 = t * 64;
        if (t > 0) MBAR_WAIT(smem_base + SM_MBAR_PV, (t - 1) & 1);

        const float4* kg = (const float4*)(g_k + ((size_t)bh * SEQ + kt0) * DH);
        #pragma unroll
        for (int i = 0; i < 8; i++) {
            int idx = tid + i * 128;
            int r = idx >> 4, c4 = idx & 15;
            float4 v = kg[idx];
            float4 hi, lo;
            hi.x = rna_tf32(v.x); lo.x = rna_tf32(v.x - hi.x);
            hi.y = rna_tf32(v.y); lo.y = rna_tf32(v.y - hi.y);
            hi.z = rna_tf32(v.z); lo.z = rna_tf32(v.z - hi.z);
            hi.w = rna_tf32(v.w); lo.w = rna_tf32(v.w - hi.w);
            uint32_t o = SWZ128((uint32_t)(r * 128 + (c4 & 7) * 16));
            uint32_t bh_off = (c4 & 8) ? SM_KH1 : SM_KH0;
            uint32_t bl_off = (c4 & 8) ? SM_KL1 : SM_KL0;
            *(float4*)(smem + bh_off + o) = hi;
            *(float4*)(smem + bl_off + o) = lo;
        }
        #pragma unroll
        for (int i = 0; i < 8; i++) {
            int idx = tid + i * 128;
            int d = idx >> 4, kc = idx & 15;
            int c = kc >> 3, f = kc & 7;
            float4 v = *(const float4*)(g_v + ((size_t)bh * DH + d) * SEQ + kt0 + c * 32 + f * 4);
            v.x = rna_tf32(v.x); v.y = rna_tf32(v.y);
            v.z = rna_tf32(v.z); v.w = rna_tf32(v.w);
            *(float4*)(smem + SM_VT + c * 8192 + SWZ128((uint32_t)(d * 128 + f * 16))) = v;
        }
        if (tid < 64)
            keepf[tid] = (mask[b * SEQ + kt0 + tid] == 1) ? 1.f : 0.f;
        __syncthreads();

        if (wid == 0) {
            TC_FENCE_AFTER();
            if (elect_one()) {
                #pragma unroll
                for (int s = 0; s < 8; s++) {
                    uint64_t bh_d = (s < 4) ? (dKH0 + 2 * s) : (dKH1 + 2 * (s - 4));
                    uint64_t bl_d = (s < 4) ? (dKL0 + 2 * s) : (dKL1 + 2 * (s - 4));
                    mma_tf32_ts(tmem + TSP, tmem + TQH + 8 * s, bh_d, IDESC_A, s > 0);
                    mma_tf32_ts(tmem + TSP, tmem + TQL + 8 * s, bh_d, IDESC_A, true);
                    mma_tf32_ts(tmem + TSP, tmem + TQH + 8 * s, bl_d, IDESC_A, true);
                }
                TC_COMMIT(smem_base + SM_MBAR_S);
            }
        }
        MBAR_WAIT(smem_base + SM_MBAR_S, t & 1);
        TC_FENCE_AFTER();

        #pragma unroll
        for (int c = 0; c < 2; c++) {
            uint32_t sr[32];
            TC_LD_X32(sr, tmem + TSP + 32 * c);
            TC_WAIT_LD();
            uint32_t pr[32];
            #pragma unroll
            for (int r = 0; r < 32; r++) {
                float s = __uint_as_float(sr[r]);
                float p = keepf[32 * c + r] * __expf(s);
                lsum += p;
                pr[r] = rna_tf32_bits(p);
            }
            TC_ST_X32(tmem + TSP + 32 * c + warpoff, pr);
        }
        TC_WAIT_ST();
        TC_FENCE_BEFORE();
        __syncthreads();

        if (wid == 0) {
            TC_FENCE_AFTER();
            if (elect_one()) {
                #pragma unroll
                for (int s = 0; s < 8; s++) {
                    uint64_t bd = MKDESC(smem_base + SM_VT + (s >> 2) * 8192) + 2 * (s & 3);
                    mma_tf32_ts(tmem + TTO, tmem + TSP + 8 * s, bd, IDESC_A,
                                !(t == 0 && s == 0));
                }
                TC_COMMIT(smem_base + SM_MBAR_PV);
            }
        }
    }

    MBAR_WAIT(smem_base + SM_MBAR_PV, 1);
    TC_FENCE_AFTER();

    uint32_t o0[32], o1[32];
    TC_LD_X32(o0, tmem + TTO);
    TC_LD_X32(o1, tmem + TTO + 32);
    TC_WAIT_LD();
    TC_FENCE_BEFORE();

    const int sq = q0 + tid;
    const float inv = (mask[b * SEQ + sq] == 1) ? (1.f / lsum) : 0.f;
    float* op = out + ((size_t)b * SEQ + sq) * EDIM + h * DH;
    #pragma unroll
    for (int i = 0; i < 8; i++) {
        float4 v;
        v.x = __uint_as_float(o0[i*4+0]) * inv;
        v.y = __uint_as_float(o0[i*4+1]) * inv;
        v.z = __uint_as_float(o0[i*4+2]) * inv;
        v.w = __uint_as_float(o0[i*4+3]) * inv;
        *(float4*)&op[i * 4] = v;
    }
    #pragma unroll
    for (int i = 0; i < 8; i++) {
        float4 v;
        v.x = __uint_as_float(o1[i*4+0]) * inv;
        v.y = __uint_as_float(o1[i*4+1]) * inv;
        v.z = __uint_as_float(o1[i*4+2]) * inv;
        v.w = __uint_as_float(o1[i*4+3]) * inv;
        *(float4*)&op[32 + i * 4] = v;
    }

    __syncthreads();
    if (wid == 0) TC_DEALLOC(tmem, 256);

#else  // ---------------- fp32 fallback (non-'a' compile pass) ----------------
    float* ks    = (float*)smem;
    float* vs    = (float*)(smem + 16384);
    float* keepf = (float*)(smem + 32768);

    const int sq = q0 + tid;
    const float* qptr = g_q + ((size_t)bh * SEQ + sq) * DH;
    float q[DH];
    #pragma unroll
    for (int d = 0; d < DH; d += 4) {
        float4 t4 = *(const float4*)&qptr[d];
        q[d+0] = t4.x * 0.125f; q[d+1] = t4.y * 0.125f;
        q[d+2] = t4.z * 0.125f; q[d+3] = t4.w * 0.125f;
    }
    float lsum = 0.f;
    float acc[DH];
    #pragma unroll
    for (int d = 0; d < DH; d++) acc[d] = 0.f;

    for (int kt0 = 0; kt0 < SEQ; kt0 += 64) {
        __syncthreads();
        const float4* kg = (const float4*)(g_k + ((size_t)bh * SEQ + kt0) * DH);
        #pragma unroll
        for (int i = 0; i < 8; i++) {
            int idx = tid + i * 128;
            ((float4*)ks)[idx] = kg[idx];
            int d = idx >> 4, f = idx & 15;
            float4 v = *(const float4*)(g_v + ((size_t)bh * DH + d) * SEQ + kt0 + f * 4);
            vs[(f*4+0)*64 + d] = v.x; vs[(f*4+1)*64 + d] = v.y;
            vs[(f*4+2)*64 + d] = v.z; vs[(f*4+3)*64 + d] = v.w;
        }
        if (tid < 64)
            keepf[tid] = (mask[b * SEQ + kt0 + tid] == 1) ? 1.f : 0.f;
        __syncthreads();

        for (int j = 0; j < 64; j++) {
            const float* kr = ks + j * 64;
            float s = 0.f;
            #pragma unroll
            for (int d = 0; d < DH; d++) s += q[d] * kr[d];
            float p = keepf[j] * __expf(s);
            lsum += p;
            const float* vr = vs + j * 64;
            #pragma unroll
            for (int d = 0; d < DH; d++) acc[d] += p * vr[d];
        }
    }
    const float inv = (mask[b * SEQ + sq] == 1) ? (1.f / lsum) : 0.f;
    float* op = out + ((size_t)b * SEQ + sq) * EDIM + h * DH;
    #pragma unroll
    for (int d = 0; d < DH; d++) op[d] = acc[d] * inv;
#endif
}

// ===========================================================================
extern "C" void kernel_launch(void* const* d_in, const int* in_sizes, int n_in,
                              void* d_out, int out_size)
{
    const float* x     = (const float*)d_in[0];
    const float* etype = (const float*)d_in[1];
    const int*   mask  = (const int*)  d_in[2];
    const float* Wq    = (const float*)d_in[3];
    const float* bq    = (const float*)d_in[4];
    const float* Wk    = (const float*)d_in[5];
    const float* bk    = (const float*)d_in[6];
    const float* Wv    = (const float*)d_in[7];
    const float* bv    = (const float*)d_in[8];
    float* out = (float*)d_out;

    static int smem_set = 0;
    if (!smem_set) {
        cudaFuncSetAttribute(tc_gemm, cudaFuncAttributeMaxDynamicSharedMemorySize, GT_TOTAL);
        cudaFuncSetAttribute(attn_tc, cudaFuncAttributeMaxDynamicSharedMemorySize, SM_TOTAL);
        smem_set = 1;
    }

    cvt_wt<<<dim3(16, 16, 3), 256>>>(Wq, Wk, Wv);

    dim3 ggrid(MROWS / 128, (3 * EDIM) / 64);    // 64 x 24
    tc_gemm<<<ggrid, 128, GT_TOTAL>>>(x, etype, bq, bk, bv);

    dim3 agrid(SEQ / 128, BATCH * HEADS);        // 16 x 32
    attn_tc<<<agrid, 128, SM_TOTAL>>>(mask, out);
}

// round 9
// speedup vs baseline: 5.5673x; 1.0154x over previous
#include <cuda_runtime.h>
#include <cuda_bf16.h>
#include <cstdint>

// Problem constants
#define BATCH 4
#define SEQ   2048
#define FDIM  512
#define EDIM  512
#define HEADS 8
#define DH    64
#define MROWS (BATCH*SEQ)      // 8192

// tcgen05 only exists in arch-accelerated ('a') compilation passes.
#if defined(__CUDA_ARCH_FEAT_SM103_ALL) || defined(__CUDA_ARCH_FEAT_SM100_ALL) || \
    defined(__CUDA_ARCH_SPECIFIC__) || defined(__CUDA_ARCH_FAMILY_SPECIFIC__)
#define TC_ENABLED 1
#else
#define TC_ENABLED 0
#endif

// Scratch: Q/K in [B,H,S,DH]; V stored TRANSPOSED [B,H,DH,S] for the PV MMA.
__device__ float g_q[(size_t)BATCH*HEADS*SEQ*DH];
__device__ float g_k[(size_t)BATCH*HEADS*SEQ*DH];
__device__ float g_v[(size_t)BATCH*HEADS*DH*SEQ];
// W^T concat [1536 n][512 k] fp32 (Wq^T | Wk^T | Wv^T), written by cvt_wt.
__device__ float g_wt[(size_t)3*EDIM*FDIM];

// ===========================================================================
// PTX helpers
// ===========================================================================
__device__ __forceinline__ uint32_t smem_u32(const void* p) {
    uint32_t a;
    asm("{ .reg .u64 t; cvta.to.shared.u64 t, %1; cvt.u32.u64 %0, t; }" : "=r"(a) : "l"(p));
    return a;
}
__device__ __forceinline__ bool elect_one() {
    uint32_t pred;
    asm volatile("{\n\t.reg .pred p;\n\telect.sync _|p, 0xFFFFFFFF;\n\t"
                 "selp.b32 %0, 1, 0, p;\n\t}" : "=r"(pred));
    return pred != 0;
}
__device__ __forceinline__ float rna_tf32(float x) {
    uint32_t u;
    asm("cvt.rna.tf32.f32 %0, %1;" : "=r"(u) : "f"(x));
    return __uint_as_float(u);
}
__device__ __forceinline__ uint32_t rna_tf32_bits(float x) {
    uint32_t u;
    asm("cvt.rna.tf32.f32 %0, %1;" : "=r"(u) : "f"(x));
    return u;
}

#define TC_ALLOC(smem_addr, n) \
    asm volatile("tcgen05.alloc.cta_group::1.sync.aligned.shared::cta.b32 [%0], %1;" \
                 :: "r"(smem_addr), "r"((uint32_t)(n)) : "memory")
#define TC_RELINQ() \
    asm volatile("tcgen05.relinquish_alloc_permit.cta_group::1.sync.aligned;")
#define TC_DEALLOC(tmem_addr, n) \
    asm volatile("tcgen05.dealloc.cta_group::1.sync.aligned.b32 %0, %1;" \
                 :: "r"(tmem_addr), "r"((uint32_t)(n)))
#define TC_WAIT_ST() asm volatile("tcgen05.wait::st.sync.aligned;" ::: "memory")
#define TC_WAIT_LD() asm volatile("tcgen05.wait::ld.sync.aligned;" ::: "memory")
#define TC_FENCE_BEFORE() asm volatile("tcgen05.fence::before_thread_sync;" ::: "memory")
#define TC_FENCE_AFTER()  asm volatile("tcgen05.fence::after_thread_sync;" ::: "memory")
#define TC_COMMIT(mbar) \
    asm volatile("tcgen05.commit.cta_group::1.mbarrier::arrive::one.shared::cluster.b64 [%0];" \
                 :: "r"((uint32_t)(mbar)) : "memory")

#define TC_ST_X32(tmem_addr, r) \
    asm volatile("tcgen05.st.sync.aligned.32x32b.x32.b32 [%0], " \
        "{%1, %2, %3, %4, %5, %6, %7, %8, %9, %10, %11, %12, %13, %14, %15, %16, " \
        " %17, %18, %19, %20, %21, %22, %23, %24, %25, %26, %27, %28, %29, %30, %31, %32};" \
        :: "r"(tmem_addr), \
           "r"((r)[0]),"r"((r)[1]),"r"((r)[2]),"r"((r)[3]),"r"((r)[4]),"r"((r)[5]),"r"((r)[6]),"r"((r)[7]), \
           "r"((r)[8]),"r"((r)[9]),"r"((r)[10]),"r"((r)[11]),"r"((r)[12]),"r"((r)[13]),"r"((r)[14]),"r"((r)[15]), \
           "r"((r)[16]),"r"((r)[17]),"r"((r)[18]),"r"((r)[19]),"r"((r)[20]),"r"((r)[21]),"r"((r)[22]),"r"((r)[23]), \
           "r"((r)[24]),"r"((r)[25]),"r"((r)[26]),"r"((r)[27]),"r"((r)[28]),"r"((r)[29]),"r"((r)[30]),"r"((r)[31]) \
        : "memory")

#define TC_LD_X32(r, tmem_addr) \
    asm volatile("tcgen05.ld.sync.aligned.32x32b.x32.b32 " \
        "{%0, %1, %2, %3, %4, %5, %6, %7, %8, %9, %10, %11, %12, %13, %14, %15, " \
        " %16, %17, %18, %19, %20, %21, %22, %23, %24, %25, %26, %27, %28, %29, %30, %31}, [%32];" \
        : "=r"((r)[0]),"=r"((r)[1]),"=r"((r)[2]),"=r"((r)[3]),"=r"((r)[4]),"=r"((r)[5]),"=r"((r)[6]),"=r"((r)[7]), \
          "=r"((r)[8]),"=r"((r)[9]),"=r"((r)[10]),"=r"((r)[11]),"=r"((r)[12]),"=r"((r)[13]),"=r"((r)[14]),"=r"((r)[15]), \
          "=r"((r)[16]),"=r"((r)[17]),"=r"((r)[18]),"=r"((r)[19]),"=r"((r)[20]),"=r"((r)[21]),"=r"((r)[22]),"=r"((r)[23]), \
          "=r"((r)[24]),"=r"((r)[25]),"=r"((r)[26]),"=r"((r)[27]),"=r"((r)[28]),"=r"((r)[29]),"=r"((r)[30]),"=r"((r)[31]) \
        : "r"(tmem_addr))

#define MBAR_INIT(mbar, cnt) \
    asm volatile("mbarrier.init.shared.b64 [%0], %1;" :: "r"((uint32_t)(mbar)), "r"((uint32_t)(cnt)) : "memory")

#define MBAR_WAIT(mbar, parity) do { \
    uint32_t _m = (uint32_t)(mbar); uint32_t _p = (uint32_t)(parity); uint32_t _done; \
    asm volatile("{\n\t.reg .pred p;\n\t" \
        "mbarrier.try_wait.parity.acquire.cta.shared::cta.b64 p, [%1], %2;\n\t" \
        "selp.b32 %0, 1, 0, p;\n\t}" : "=r"(_done) : "r"(_m), "r"(_p) : "memory"); \
    if (!_done) { \
        asm volatile("{\n\t.reg .pred P1;\n\t" \
            "WAIT_LOOP_%=:\n\t" \
            "mbarrier.try_wait.parity.acquire.cta.shared::cta.b64 P1, [%0], %1, 0x989680;\n\t" \
            "@P1 bra.uni WAIT_DONE_%=;\n\t" \
            "bra.uni WAIT_LOOP_%=;\n\t" \
            "WAIT_DONE_%=:\n\t}" :: "r"(_m), "r"(_p) : "memory"); \
    } \
} while (0)

// SW128 SMEM descriptor (layout=2, version=1, SBO=64, LBO=1)
#define SMEM_DESC_BASE_SW128 \
    ((uint64_t(2) << 61) | (uint64_t(1) << 46) | (uint64_t(64) << 32) | (uint64_t(1) << 16))
#define MKDESC(addr) (SMEM_DESC_BASE_SW128 | ((uint64_t)((addr) >> 4) & 0x3FFF))
#define SWZ128(o) ((o) ^ (((o) >> 3) & 0x70))

#if TC_ENABLED
__device__ __forceinline__ void mma_tf32_ts(uint32_t d, uint32_t a, uint64_t bdesc,
                                            uint32_t idesc, bool acc) {
    uint32_t e = acc ? 1u : 0u;
    asm volatile("{\n\t.reg .pred p;\n\tsetp.ne.u32 p, %4, 0;\n\t"
        "tcgen05.mma.cta_group::1.kind::tf32 [%0], [%1], %2, %3, p;\n\t}"
        :: "r"(d), "r"(a), "l"(bdesc), "r"(idesc), "r"(e) : "memory");
}
#endif

// idesc: dtype=F32(1@4), atype=TF32(2@7), btype=TF32(2@10), N>>3@17, M>>4@24
// M=128, N=64 — proven constant.
#define IDESC_A ((1u<<4)|(2u<<7)|(2u<<10)|((64u/8)<<17)|((128u/16)<<24))

// ===========================================================================
// cvt_wt: W [512k x 512n] -> g_wt [n][k], rows concat over q/k/v. (proven)
// ===========================================================================
__global__ __launch_bounds__(256)
void cvt_wt(const float* __restrict__ Wq, const float* __restrict__ Wk,
            const float* __restrict__ Wv)
{
    __shared__ float t[32][33];
    const int z = blockIdx.z;
    const float* W = (z == 0) ? Wq : (z == 1) ? Wk : Wv;
    const int k0 = blockIdx.x * 32;
    const int n0 = blockIdx.y * 32;
    const int tx = threadIdx.x & 31;
    const int ty = threadIdx.x >> 5;
    #pragma unroll
    for (int i = 0; i < 4; i++)
        t[ty + 8*i][tx] = W[(size_t)(k0 + ty + 8*i) * EDIM + n0 + tx];
    __syncthreads();
    #pragma unroll
    for (int i = 0; i < 4; i++)
        g_wt[(size_t)(z * EDIM + n0 + ty + 8*i) * FDIM + k0 + tx] = t[tx][ty + 8*i];
}

// ===========================================================================
// tcgen05 tf32x3 projection GEMM (round-8 PROVEN, unchanged).
// ===========================================================================
#define TXH 0
#define TXL 64
#define TD  128
#define GT_TMEMPTR 0
#define GT_MBAR    16
#define GT_BIAS    64
#define GT_WH0     1024
#define GT_WH1     (GT_WH0 + 8192)
#define GT_WL0     (GT_WH1 + 8192)
#define GT_WL1     (GT_WL0 + 8192)
#define GT_TOTAL   (GT_WL1 + 8192)     // 33792

__global__ __launch_bounds__(128)
void tc_gemm(const float* __restrict__ x,
             const float* __restrict__ etype,
             const float* __restrict__ bq, const float* __restrict__ bk,
             const float* __restrict__ bv)
{
    extern __shared__ char sm[];
    const int tid = threadIdx.x;
    const int m0 = blockIdx.x * 128;
    const int n0g = blockIdx.y * 64;
    const int which = n0g >> 9;
    const int e0 = n0g & 511;
    const int hh = e0 >> 6;
    const float* bias = (which == 0) ? bq : (which == 1) ? bk : bv;

#if TC_ENABLED
    const uint32_t base = smem_u32(sm);
    const int wid = tid >> 5;
    const uint32_t warpoff = (uint32_t)wid << 21;

    if (wid == 0) { TC_ALLOC(base + GT_TMEMPTR, 256); TC_RELINQ(); }
    __syncthreads();
    uint32_t tmem;
    asm volatile("ld.shared.b32 %0, [%1];" : "=r"(tmem) : "r"(base + GT_TMEMPTR));
    if (tid == 0) MBAR_INIT(base + GT_MBAR, 1);
    if (tid < 64) ((float*)(sm + GT_BIAS))[tid] = bias[e0 + tid];
    __syncthreads();

    const uint64_t dWH0 = MKDESC(base + GT_WH0);
    const uint64_t dWH1 = MKDESC(base + GT_WH1);
    const uint64_t dWL0 = MKDESC(base + GT_WL0);
    const uint64_t dWL1 = MKDESC(base + GT_WL1);

    for (int c = 0; c < 8; c++) {
        const int k0 = c * 64;
        #pragma unroll
        for (int i = 0; i < 8; i++) {
            int idx = tid + i * 128;
            int r = idx >> 4, c4 = idx & 15;
            float4 v = *(const float4*)&g_wt[(size_t)(n0g + r) * FDIM + k0 + c4 * 4];
            float4 hi, lo;
            hi.x = rna_tf32(v.x); lo.x = rna_tf32(v.x - hi.x);
            hi.y = rna_tf32(v.y); lo.y = rna_tf32(v.y - hi.y);
            hi.z = rna_tf32(v.z); lo.z = rna_tf32(v.z - hi.z);
            hi.w = rna_tf32(v.w); lo.w = rna_tf32(v.w - hi.w);
            uint32_t o = SWZ128((uint32_t)(r * 128 + (c4 & 7) * 16));
            uint32_t bh_off = (c4 & 8) ? GT_WH1 : GT_WH0;
            uint32_t bl_off = (c4 & 8) ? GT_WL1 : GT_WL0;
            *(float4*)(sm + bh_off + o) = hi;
            *(float4*)(sm + bl_off + o) = lo;
        }
        {
            const float4* xp = (const float4*)(x + (size_t)(m0 + tid) * FDIM + k0);
            uint32_t rh[64], rl[64];
            #pragma unroll
            for (int i = 0; i < 16; i++) {
                float4 v = xp[i];
                float f[4] = { v.x, v.y, v.z, v.w };
                #pragma unroll
                for (int cc = 0; cc < 4; cc++) {
                    float hi = rna_tf32(f[cc]);
                    rh[i*4+cc] = __float_as_uint(hi);
                    rl[i*4+cc] = rna_tf32_bits(f[cc] - hi);
                }
            }
            TC_ST_X32(tmem + TXH + warpoff, rh);
            TC_ST_X32(tmem + TXH + 32 + warpoff, rh + 32);
            TC_ST_X32(tmem + TXL + warpoff, rl);
            TC_ST_X32(tmem + TXL + 32 + warpoff, rl + 32);
            TC_WAIT_ST();
        }
        TC_FENCE_BEFORE();
        __syncthreads();

        if (wid == 0) {
            TC_FENCE_AFTER();
            if (elect_one()) {
                #pragma unroll
                for (int s = 0; s < 8; s++) {
                    uint64_t bh_d = (s < 4) ? (dWH0 + 2 * s) : (dWH1 + 2 * (s - 4));
                    uint64_t bl_d = (s < 4) ? (dWL0 + 2 * s) : (dWL1 + 2 * (s - 4));
                    mma_tf32_ts(tmem + TD, tmem + TXH + 8 * s, bh_d, IDESC_A,
                                !(c == 0 && s == 0));
                    mma_tf32_ts(tmem + TD, tmem + TXL + 8 * s, bh_d, IDESC_A, true);
                    mma_tf32_ts(tmem + TD, tmem + TXH + 8 * s, bl_d, IDESC_A, true);
                }
                TC_COMMIT(base + GT_MBAR);
            }
        }
        MBAR_WAIT(base + GT_MBAR, c & 1);
        TC_FENCE_AFTER();
        __syncthreads();
    }

    uint32_t d0[32], d1[32];
    TC_LD_X32(d0, tmem + TD);
    TC_LD_X32(d1, tmem + TD + 32);
    TC_WAIT_LD();
    TC_FENCE_BEFORE();

    const int bb = m0 >> 11;
    const int sidx = (m0 & 2047) + tid;
    const float* bs = (const float*)(sm + GT_BIAS);

    if (which != 2) {
        float* outbuf = (which == 0) ? g_q : g_k;
        float* rowp = outbuf + ((size_t)(bb * HEADS + hh) * SEQ + sidx) * DH;
        const float* ep = (which == 0)
            ? etype + (size_t)(m0 + tid) * EDIM + e0 : nullptr;
        #pragma unroll
        for (int n4 = 0; n4 < 16; n4++) {
            const uint32_t* dr = (n4 < 8) ? d0 : d1;
            int j = (n4 & 7) * 4;
            float4 v;
            v.x = __uint_as_float(dr[j+0]) + bs[n4*4+0];
            v.y = __uint_as_float(dr[j+1]) + bs[n4*4+1];
            v.z = __uint_as_float(dr[j+2]) + bs[n4*4+2];
            v.w = __uint_as_float(dr[j+3]) + bs[n4*4+3];
            if (which == 0) {
                float4 e4 = *(const float4*)&ep[n4*4];
                v.x += e4.x; v.y += e4.y; v.z += e4.z; v.w += e4.w;
            }
            *(float4*)&rowp[n4*4] = v;
        }
    } else {
        float* vb = g_v + ((size_t)(bb * HEADS + hh) * DH) * SEQ + sidx;
        #pragma unroll
        for (int n = 0; n < 32; n++)
            vb[(size_t)n * SEQ] = __uint_as_float(d0[n]) + bs[n];
        #pragma unroll
        for (int n = 0; n < 32; n++)
            vb[(size_t)(n + 32) * SEQ] = __uint_as_float(d1[n]) + bs[n + 32];
    }
    __syncthreads();
    if (wid == 0) TC_DEALLOC(tmem, 256);

#else  // ------------- fp32 fallback GEMM (non-'a' compile pass) -------------
    const int bb = m0 >> 11;
    const int sidx = (m0 & 2047) + tid;
    float acc[64];
    #pragma unroll
    for (int n = 0; n < 64; n++) acc[n] = 0.f;
    for (int k = 0; k < FDIM; k++) {
        float a = x[(size_t)(m0 + tid) * FDIM + k];
        #pragma unroll 16
        for (int n = 0; n < 64; n++)
            acc[n] += a * g_wt[(size_t)(n0g + n) * FDIM + k];
    }
    if (which != 2) {
        float* outbuf = (which == 0) ? g_q : g_k;
        float* rowp = outbuf + ((size_t)(bb * HEADS + hh) * SEQ + sidx) * DH;
        for (int n = 0; n < 64; n++) {
            float v = acc[n] + bias[e0 + n];
            if (which == 0) v += etype[(size_t)(m0 + tid) * EDIM + e0 + n];
            rowp[n] = v;
        }
    } else {
        float* vb = g_v + ((size_t)(bb * HEADS + hh) * DH) * SEQ + sidx;
        for (int n = 0; n < 64; n++)
            vb[(size_t)n * SEQ] = acc[n] + bias[e0 + n];
    }
#endif
}

// ===========================================================================
// tcgen05 tf32x3 attention — double-buffered staging + 256 threads.
// TMEM: Qhi[0..63], Qlo[64..127], S/P in place [128..191], O [192..255].
// SMEM: two 48KB buffers (KH0,KH1,KL0,KL1,VT), staged one tile ahead.
// ===========================================================================
#define TQH 0
#define TQL 64
#define TSP 128
#define TTO 192
#define SM_TMEMPTR 0
#define SM_MBAR_S  16
#define SM_MBAR_PV 24
#define SM_KEEP0   64                  // keep buf0: 64 floats
#define SM_KEEP1   320                 // keep buf1
#define SM_LSUM    576                 // 256 floats
#define SM_BUF0    2048
#define BUFSZ      49152               // KH0+KH1+KL0+KL1 (32KB) + VT (16KB)
#define OFF_KH0    0
#define OFF_KH1    8192
#define OFF_KL0    16384
#define OFF_KL1    24576
#define OFF_VT     32768
#define SM_TOTAL   (SM_BUF0 + 2*BUFSZ) // 100352

__global__ __launch_bounds__(256, 2)
void attn_tc(const int* __restrict__ mask, float* __restrict__ out)
{
    extern __shared__ char smem[];
    const int tid = threadIdx.x;
    const int bh = blockIdx.y, b = bh >> 3, h = bh & 7;
    const int q0 = blockIdx.x * 128;

#if TC_ENABLED
    const uint32_t smem_base = smem_u32(smem);
    const int wid = tid >> 5;
    const uint32_t warpoff = (uint32_t)(wid & 3) << 21;

    if (wid == 0) { TC_ALLOC(smem_base + SM_TMEMPTR, 256); TC_RELINQ(); }
    __syncthreads();
    uint32_t tmem;
    asm volatile("ld.shared.b32 %0, [%1];" : "=r"(tmem) : "r"(smem_base + SM_TMEMPTR));

    if (tid == 0) {
        MBAR_INIT(smem_base + SM_MBAR_S, 1);
        MBAR_INIT(smem_base + SM_MBAR_PV, 1);
    }

    // Q -> TMEM hi/lo (warps 0-3; thread tid = query row; 32-col passes)
    if (tid < 128) {
        const float4* qp = (const float4*)(g_q + ((size_t)bh * SEQ + q0 + tid) * DH);
        #pragma unroll
        for (int half = 0; half < 2; half++) {
            uint32_t rh[32], rl[32];
            #pragma unroll
            for (int i = 0; i < 8; i++) {
                float4 v = qp[half * 8 + i];
                float f[4] = { v.x * 0.125f, v.y * 0.125f, v.z * 0.125f, v.w * 0.125f };
                #pragma unroll
                for (int c = 0; c < 4; c++) {
                    float hi = rna_tf32(f[c]);
                    rh[i*4+c] = __float_as_uint(hi);
                    rl[i*4+c] = rna_tf32_bits(f[c] - hi);
                }
            }
            TC_ST_X32(tmem + TQH + half * 32 + warpoff, rh);
            TC_ST_X32(tmem + TQL + half * 32 + warpoff, rl);
        }
        TC_WAIT_ST();
        TC_FENCE_BEFORE();
    }

    // Stage tile 0 into buffer 0 (all 256 threads)
    {
        const uint32_t bufb = SM_BUF0;
        const float4* kg = (const float4*)(g_k + (size_t)bh * SEQ * DH);
        #pragma unroll
        for (int i = 0; i < 4; i++) {
            int idx = tid + i * 256;
            int r = idx >> 4, c4 = idx & 15;
            float4 v = kg[idx];
            float4 hi, lo;
            hi.x = rna_tf32(v.x); lo.x = rna_tf32(v.x - hi.x);
            hi.y = rna_tf32(v.y); lo.y = rna_tf32(v.y - hi.y);
            hi.z = rna_tf32(v.z); lo.z = rna_tf32(v.z - hi.z);
            hi.w = rna_tf32(v.w); lo.w = rna_tf32(v.w - hi.w);
            uint32_t o = SWZ128((uint32_t)(r * 128 + (c4 & 7) * 16));
            uint32_t hsel = (c4 & 8) ? 8192u : 0u;
            *(float4*)(smem + bufb + OFF_KH0 + hsel + o) = hi;
            *(float4*)(smem + bufb + OFF_KL0 + hsel + o) = lo;
        }
        #pragma unroll
        for (int i = 0; i < 4; i++) {
            int idx = tid + i * 256;
            int d = idx >> 4, kc = idx & 15;
            int c = kc >> 3, f = kc & 7;
            float4 v = *(const float4*)(g_v + ((size_t)bh * DH + d) * SEQ + c * 32 + f * 4);
            v.x = rna_tf32(v.x); v.y = rna_tf32(v.y);
            v.z = rna_tf32(v.z); v.w = rna_tf32(v.w);
            *(float4*)(smem + bufb + OFF_VT + c * 8192 + SWZ128((uint32_t)(d * 128 + f * 16))) = v;
        }
        if (tid < 64)
            ((float*)(smem + SM_KEEP0))[tid] = (mask[b * SEQ + tid] == 1) ? 1.f : 0.f;
    }
    __syncthreads();

    // Per-buffer descriptors
    uint64_t dKH0[2], dKH1[2], dKL0[2], dKL1[2];
    #pragma unroll
    for (int bf = 0; bf < 2; bf++) {
        uint32_t bb2 = smem_base + SM_BUF0 + bf * BUFSZ;
        dKH0[bf] = MKDESC(bb2 + OFF_KH0);
        dKH1[bf] = MKDESC(bb2 + OFF_KH1);
        dKL0[bf] = MKDESC(bb2 + OFF_KL0);
        dKL1[bf] = MKDESC(bb2 + OFF_KL1);
    }

    float lsum = 0.f;
    const int colbase = (wid >> 2) * 32;     // 0 or 32

    for (int t = 0; t < 32; t++) {
        const int cur = t & 1;
        // PV(t-1) completion protects TSP (in-place S/P) and buffer cur^1.
        if (t > 0) MBAR_WAIT(smem_base + SM_MBAR_PV, (t - 1) & 1);

        // Issue S(t) from buffer cur
        if (wid == 0) {
            TC_FENCE_AFTER();
            if (elect_one()) {
                #pragma unroll
                for (int s = 0; s < 8; s++) {
                    uint64_t bh_d = (s < 4) ? (dKH0[cur] + 2 * s) : (dKH1[cur] + 2 * (s - 4));
                    uint64_t bl_d = (s < 4) ? (dKL0[cur] + 2 * s) : (dKL1[cur] + 2 * (s - 4));
                    mma_tf32_ts(tmem + TSP, tmem + TQH + 8 * s, bh_d, IDESC_A, s > 0);
                    mma_tf32_ts(tmem + TSP, tmem + TQL + 8 * s, bh_d, IDESC_A, true);
                    mma_tf32_ts(tmem + TSP, tmem + TQH + 8 * s, bl_d, IDESC_A, true);
                }
                TC_COMMIT(smem_base + SM_MBAR_S);
            }
        }

        // Stage tile t+1 into buffer cur^1 while S(t) runs (PV(t-1) already done)
        if (t < 31) {
            const int kt1 = (t + 1) * 64;
            const uint32_t bufb = SM_BUF0 + (cur ^ 1) * BUFSZ;
            const float4* kg = (const float4*)(g_k + ((size_t)bh * SEQ + kt1) * DH);
            #pragma unroll
            for (int i = 0; i < 4; i++) {
                int idx = tid + i * 256;
                int r = idx >> 4, c4 = idx & 15;
                float4 v = kg[idx];
                float4 hi, lo;
                hi.x = rna_tf32(v.x); lo.x = rna_tf32(v.x - hi.x);
                hi.y = rna_tf32(v.y); lo.y = rna_tf32(v.y - hi.y);
                hi.z = rna_tf32(v.z); lo.z = rna_tf32(v.z - hi.z);
                hi.w = rna_tf32(v.w); lo.w = rna_tf32(v.w - hi.w);
                uint32_t o = SWZ128((uint32_t)(r * 128 + (c4 & 7) * 16));
                uint32_t hsel = (c4 & 8) ? 8192u : 0u;
                *(float4*)(smem + bufb + OFF_KH0 + hsel + o) = hi;
                *(float4*)(smem + bufb + OFF_KL0 + hsel + o) = lo;
            }
            #pragma unroll
            for (int i = 0; i < 4; i++) {
                int idx = tid + i * 256;
                int d = idx >> 4, kc = idx & 15;
                int c = kc >> 3, f = kc & 7;
                float4 v = *(const float4*)(g_v + ((size_t)bh * DH + d) * SEQ + kt1 + c * 32 + f * 4);
                v.x = rna_tf32(v.x); v.y = rna_tf32(v.y);
                v.z = rna_tf32(v.z); v.w = rna_tf32(v.w);
                *(float4*)(smem + bufb + OFF_VT + c * 8192 + SWZ128((uint32_t)(d * 128 + f * 16))) = v;
            }
            if (tid < 64) {
                float* kp = (float*)(smem + ((cur ^ 1) ? SM_KEEP1 : SM_KEEP0));
                kp[tid] = (mask[b * SEQ + kt1 + tid] == 1) ? 1.f : 0.f;
            }
        }

        // Wait S(t), exp in place (8 warps: subpartition wid&3, cols colbase..+31)
        MBAR_WAIT(smem_base + SM_MBAR_S, t & 1);
        TC_FENCE_AFTER();
        {
            const float* keepf = (const float*)(smem + (cur ? SM_KEEP1 : SM_KEEP0));
            uint32_t sr[32];
            TC_LD_X32(sr, tmem + TSP + colbase);
            TC_WAIT_LD();
            uint32_t pr[32];
            #pragma unroll
            for (int r = 0; r < 32; r++) {
                float s = __uint_as_float(sr[r]);
                float p = keepf[colbase + r] * __expf(s);
                lsum += p;
                pr[r] = rna_tf32_bits(p);
            }
            TC_ST_X32(tmem + TSP + colbase + warpoff, pr);
        }
        TC_WAIT_ST();
        TC_FENCE_BEFORE();
        __syncthreads();

        // Issue PV(t) from buffer cur
        if (wid == 0) {
            TC_FENCE_AFTER();
            if (elect_one()) {
                #pragma unroll
                for (int s = 0; s < 8; s++) {
                    uint64_t bd = MKDESC(smem_base + SM_BUF0 + cur * BUFSZ + OFF_VT
                                         + (s >> 2) * 8192) + 2 * (s & 3);
                    mma_tf32_ts(tmem + TTO, tmem + TSP + 8 * s, bd, IDESC_A,
                                !(t == 0 && s == 0));
                }
                TC_COMMIT(smem_base + SM_MBAR_PV);
            }
        }
    }

    MBAR_WAIT(smem_base + SM_MBAR_PV, 1);    // 32nd commit -> parity 1
    TC_FENCE_AFTER();

    // Combine lsum halves (cols 0-31 in warps 0-3, cols 32-63 in warps 4-7)
    float* lsums = (float*)(smem + SM_LSUM);
    lsums[tid] = lsum;
    __syncthreads();

    if (tid < 128) {
        const float ltot = lsums[tid] + lsums[tid + 128];
        uint32_t o0[32], o1[32];
        TC_LD_X32(o0, tmem + TTO);
        TC_LD_X32(o1, tmem + TTO + 32);
        TC_WAIT_LD();
        TC_FENCE_BEFORE();

        const int sq = q0 + tid;
        const float inv = (mask[b * SEQ + sq] == 1) ? (1.f / ltot) : 0.f;
        float* op = out + ((size_t)b * SEQ + sq) * EDIM + h * DH;
        #pragma unroll
        for (int i = 0; i < 8; i++) {
            float4 v;
            v.x = __uint_as_float(o0[i*4+0]) * inv;
            v.y = __uint_as_float(o0[i*4+1]) * inv;
            v.z = __uint_as_float(o0[i*4+2]) * inv;
            v.w = __uint_as_float(o0[i*4+3]) * inv;
            *(float4*)&op[i * 4] = v;
        }
        #pragma unroll
        for (int i = 0; i < 8; i++) {
            float4 v;
            v.x = __uint_as_float(o1[i*4+0]) * inv;
            v.y = __uint_as_float(o1[i*4+1]) * inv;
            v.z = __uint_as_float(o1[i*4+2]) * inv;
            v.w = __uint_as_float(o1[i*4+3]) * inv;
            *(float4*)&op[32 + i * 4] = v;
        }
    }

    __syncthreads();
    if (wid == 0) TC_DEALLOC(tmem, 256);

#else  // ---------------- fp32 fallback (non-'a' compile pass) ----------------
    float* ks    = (float*)smem;              // [64][64]
    float* vs    = (float*)(smem + 16384);
    float* keepf = (float*)(smem + 32768);

    const int sq = q0 + (tid & 127);
    const float* qptr = g_q + ((size_t)bh * SEQ + sq) * DH;
    float q[DH];
    #pragma unroll
    for (int d = 0; d < DH; d++) q[d] = qptr[d] * 0.125f;
    float lsum = 0.f;
    float acc[DH];
    #pragma unroll
    for (int d = 0; d < DH; d++) acc[d] = 0.f;

    for (int kt0 = 0; kt0 < SEQ; kt0 += 64) {
        __syncthreads();
        const float4* kg = (const float4*)(g_k + ((size_t)bh * SEQ + kt0) * DH);
        #pragma unroll
        for (int i = 0; i < 4; i++) {
            int idx = tid + i * 256;
            ((float4*)ks)[idx] = kg[idx];
            int d = idx >> 4, f = idx & 15;
            float4 v = *(const float4*)(g_v + ((size_t)bh * DH + d) * SEQ + kt0 + f * 4);
            vs[(f*4+0)*64 + d] = v.x; vs[(f*4+1)*64 + d] = v.y;
            vs[(f*4+2)*64 + d] = v.z; vs[(f*4+3)*64 + d] = v.w;
        }
        if (tid < 64)
            keepf[tid] = (mask[b * SEQ + kt0 + tid] == 1) ? 1.f : 0.f;
        __syncthreads();

        if (tid < 128) {
            for (int j = 0; j < 64; j++) {
                const float* kr = ks + j * 64;
                float s = 0.f;
                #pragma unroll
                for (int d = 0; d < DH; d++) s += q[d] * kr[d];
                float p = keepf[j] * __expf(s);
                lsum += p;
                const float* vr = vs + j * 64;
                #pragma unroll
                for (int d = 0; d < DH; d++) acc[d] += p * vr[d];
            }
        }
    }
    if (tid < 128) {
        const float inv = (mask[b * SEQ + sq] == 1) ? (1.f / lsum) : 0.f;
        float* op = out + ((size_t)b * SEQ + sq) * EDIM + h * DH;
        #pragma unroll
        for (int d = 0; d < DH; d++) op[d] = acc[d] * inv;
    }
#endif
}

// ===========================================================================
extern "C" void kernel_launch(void* const* d_in, const int* in_sizes, int n_in,
                              void* d_out, int out_size)
{
    const float* x     = (const float*)d_in[0];
    const float* etype = (const float*)d_in[1];
    const int*   mask  = (const int*)  d_in[2];
    const float* Wq    = (const float*)d_in[3];
    const float* bq    = (const float*)d_in[4];
    const float* Wk    = (const float*)d_in[5];
    const float* bk    = (const float*)d_in[6];
    const float* Wv    = (const float*)d_in[7];
    const float* bv    = (const float*)d_in[8];
    float* out = (float*)d_out;

    static int smem_set = 0;
    if (!smem_set) {
        cudaFuncSetAttribute(tc_gemm, cudaFuncAttributeMaxDynamicSharedMemorySize, GT_TOTAL);
        cudaFuncSetAttribute(attn_tc, cudaFuncAttributeMaxDynamicSharedMemorySize, SM_TOTAL);
        smem_set = 1;
    }

    cvt_wt<<<dim3(16, 16, 3), 256>>>(Wq, Wk, Wv);

    dim3 ggrid(MROWS / 128, (3 * EDIM) / 64);    // 64 x 24
    tc_gemm<<<ggrid, 128, GT_TOTAL>>>(x, etype, bq, bk, bv);

    dim3 agrid(SEQ / 128, BATCH * HEADS);        // 16 x 32
    attn_tc<<<agrid, 256, SM_TOTAL>>>(mask, out);
}